// round 12
// baseline (speedup 1.0000x reference)
#include <cuda_runtime.h>
#include <cuda_bf16.h>
#include <cstdint>
#include <cstddef>

// Problem constants: B=4, S=4096, D=512
#define ROWS_TOTAL 16384
#define DIMD 512
#define CCHUNK 256
#define NCHUNKS 64
#define CHUNKS_PER_BATCH 16

#define NE  ((size_t)ROWS_TOTAL * DIMD)             // 8,388,608
#define NQKV ((size_t)ROWS_TOTAL * 3 * DIMD)        // 25,165,824
#define STN ((size_t)NCHUNKS * DIMD * DIMD)         // 16,777,216
#define SCN ((size_t)NCHUNKS * CCHUNK * CCHUNK)     // 4,194,304

#define SSQ ((long)CCHUNK * CCHUNK)                 // 65536
#define CHQ ((long)CCHUNK * 3 * DIMD)               // 393216
#define CHY ((long)CCHUNK * DIMD)                   // 131072
#define STQ ((long)DIMD * DIMD)                     // 262144

typedef __nv_bfloat16 bf;

// ---------------------------------------------------------------------------
// Scratch (static device globals)
// ---------------------------------------------------------------------------
__device__ __align__(16) bf g_xh[NE], g_xl[NE];
__device__ __align__(16) bf g_qkvh[NQKV], g_qkvl[NQKV];     // [16384][1536]
__device__ __align__(16) bf g_yh[NE], g_yl[NE];
__device__ __align__(16) bf g_kth[NE], g_ktl[NE];           // [512][16384]
__device__ __align__(16) bf g_vth[NE], g_vtl[NE];
__device__ __align__(16) bf g_wth[(size_t)4 * DIMD * DIMD]; // [4][512 n][512 k] = W^T
__device__ __align__(16) bf g_wtl[(size_t)4 * DIMD * DIMD];
__device__ __align__(16) bf g_ph[STN], g_pl[STN];
__device__ __align__(16) bf g_sch[SCN], g_scl[SCN];
__device__ __align__(16) float g_st[STN];

// ---------------------------------------------------------------------------
// helpers
// ---------------------------------------------------------------------------
__device__ __forceinline__ uint32_t smem_u32(const void* p) {
    uint32_t a;
    asm("{ .reg .u64 t; cvta.to.shared.u64 t, %1; cvt.u32.u64 %0, t; }" : "=r"(a) : "l"(p));
    return a;
}
__device__ __forceinline__ void cp16(uint32_t dst, const void* src) {
    asm volatile("cp.async.cg.shared.global [%0], [%1], 16;" :: "r"(dst), "l"(src));
}
#define CP_COMMIT() asm volatile("cp.async.commit_group;" ::: "memory")
template <int N> __device__ __forceinline__ void cp_wait() {
    asm volatile("cp.async.wait_group %0;" :: "n"(N) : "memory");
}
__device__ __forceinline__ void ldm4(uint32_t* r, uint32_t addr) {
    asm volatile("ldmatrix.sync.aligned.m8n8.x4.shared.b16 {%0,%1,%2,%3}, [%4];"
                 : "=r"(r[0]), "=r"(r[1]), "=r"(r[2]), "=r"(r[3]) : "r"(addr));
}
__device__ __forceinline__ void mma16816(float* d, const uint32_t* a, uint32_t b0, uint32_t b1) {
    asm volatile("mma.sync.aligned.m16n8k16.row.col.f32.bf16.bf16.f32 "
                 "{%0,%1,%2,%3},{%4,%5,%6,%7},{%8,%9},{%0,%1,%2,%3};"
                 : "+f"(d[0]), "+f"(d[1]), "+f"(d[2]), "+f"(d[3])
                 : "r"(a[0]), "r"(a[1]), "r"(a[2]), "r"(a[3]), "r"(b0), "r"(b1));
}
__device__ __forceinline__ void split1(float v, uint16_t& h, uint16_t& l) {
    __nv_bfloat16 hb = __float2bfloat16(v);
    __nv_bfloat16 lb = __float2bfloat16(v - __bfloat162float(hb));
    h = __bfloat16_as_ushort(hb);
    l = __bfloat16_as_ushort(lb);
}
__device__ __forceinline__ void split2(float v0, float v1, uint32_t& hi, uint32_t& lo) {
    uint16_t h0, l0, h1, l1;
    split1(v0, h0, l0); split1(v1, h1, l1);
    hi = (uint32_t)h0 | ((uint32_t)h1 << 16);
    lo = (uint32_t)l0 | ((uint32_t)l1 << 16);
}

// ---------------------------------------------------------------------------
// shared GEMM core: CTA tile 128x128, 8 warps (2m x 4n), warp tile 64x32.
// C = sum_k A1*B1^T (+ sum_k A2*B2^T if K2>0), split-bf16 3-term, fp32 accum.
// 3-stage cp.async pipeline, one __syncthreads per 32-k chunk.
// All 12 fragment ldsm per kh2 hoisted into one burst -> one exposed LDSM
// latency window per kh2, then 96 uninterrupted MMAs (term-major).
// MODE 0: C f32; MODE 1: split planes; MODE 2: split planes + causal mask.
// ---------------------------------------------------------------------------
#define STAGE_BYTES 32768
#define GSMEM (3 * STAGE_BYTES)   // 96 KB -> 2 CTAs/SM

template <int MODE>
__device__ __forceinline__ void gemm_core(
    const bf* __restrict__ A1h, const bf* __restrict__ A1l, long sA1, int lda1,
    const bf* __restrict__ B1h, const bf* __restrict__ B1l, long sB1, int ldb1, int K1,
    const bf* __restrict__ A2h, const bf* __restrict__ A2l, long sA2, int lda2,
    const bf* __restrict__ B2h, const bf* __restrict__ B2l, long sB2, int ldb2, int K2,
    void* __restrict__ Chv, void* __restrict__ Clv, long sC, int ldc,
    uint32_t sm, int bm, int bn, long z)
{
    const int tid = threadIdx.x, lane = tid & 31, wid = tid >> 5;
    const int wm = wid & 1, wn = wid >> 1;      // 2 x 4

    float acc[4][4][4];
#pragma unroll
    for (int i = 0; i < 4; i++)
#pragma unroll
        for (int j = 0; j < 4; j++)
#pragma unroll
            for (int q = 0; q < 4; q++) acc[i][j][q] = 0.0f;

    auto load = [&](const bf* Ah, const bf* Al, int lda,
                    const bf* Bh, const bf* Bl, int ldb, int c, int buf) {
        const int k0 = c * 32;
        const uint32_t sb = sm + buf * STAGE_BYTES;
#pragma unroll
        for (int i = 0; i < 4; i++) {
            int e = tid + 256 * i;              // A: 1024 cp16
            int row = e >> 3, ch = e & 7;
            int kc = k0 + (ch & 3) * 8;
            const bf* src = (ch < 4 ? Ah : Al) + (long)row * lda + kc;
            uint32_t sw = (uint32_t)(row * 128 + ((ch ^ (row & 7)) << 4));
            cp16(sb + sw, src);
        }
#pragma unroll
        for (int i = 0; i < 4; i++) {
            int e = tid + 256 * i;              // B: 1024 cp16
            int row = e >> 3, ch = e & 7;
            int kc = k0 + (ch & 3) * 8;
            const bf* src = (ch < 4 ? Bh : Bl) + (long)row * ldb + kc;
            uint32_t sw = (uint32_t)(row * 128 + ((ch ^ (row & 7)) << 4));
            cp16(sb + 16384 + sw, src);
        }
    };

    auto compute = [&](int buf) {
        const uint32_t ba = sm + buf * STAGE_BYTES;
        const uint32_t bb = ba + 16384;
#pragma unroll
        for (int kh2 = 0; kh2 < 2; kh2++) {
            uint32_t ahf[4][4], alf[4][4], bhf[2][4], blf[2][4];
            // ---- one ldsm burst: 8 A + 4 B, all independent ----
            {
                int arow = wm * 64 + (lane & 7) + ((lane >> 3) & 1) * 8;
                int ach = kh2 * 2 + (lane >> 4);
#pragma unroll
                for (int mf = 0; mf < 4; mf++) {
                    int row = arow + mf * 16;
                    ldm4(ahf[mf], ba + row * 128 + ((ach ^ (row & 7)) << 4));
                }
#pragma unroll
                for (int mf = 0; mf < 4; mf++) {
                    int row = arow + mf * 16;
                    ldm4(alf[mf], ba + row * 128 + (((ach + 4) ^ (row & 7)) << 4));
                }
                int brow0 = wn * 32 + (lane & 7) + (lane >> 4) * 8;
                int bch = kh2 * 2 + ((lane >> 3) & 1);
#pragma unroll
                for (int bi = 0; bi < 2; bi++) {
                    int row = brow0 + bi * 16;
                    ldm4(bhf[bi], bb + row * 128 + ((bch ^ (row & 7)) << 4));
                }
#pragma unroll
                for (int bi = 0; bi < 2; bi++) {
                    int row = brow0 + bi * 16;
                    ldm4(blf[bi], bb + row * 128 + (((bch + 4) ^ (row & 7)) << 4));
                }
            }
            // ---- 96 uninterrupted MMAs, term-major ----
            // per-acc order stays hh, hl, lh -> bitwise identical.
#pragma unroll
            for (int mf = 0; mf < 4; mf++)
#pragma unroll
                for (int nf = 0; nf < 4; nf++)
                    mma16816(acc[mf][nf], ahf[mf], bhf[nf >> 1][2 * (nf & 1)], bhf[nf >> 1][2 * (nf & 1) + 1]);
#pragma unroll
            for (int mf = 0; mf < 4; mf++)
#pragma unroll
                for (int nf = 0; nf < 4; nf++)
                    mma16816(acc[mf][nf], ahf[mf], blf[nf >> 1][2 * (nf & 1)], blf[nf >> 1][2 * (nf & 1) + 1]);
#pragma unroll
            for (int mf = 0; mf < 4; mf++)
#pragma unroll
                for (int nf = 0; nf < 4; nf++)
                    mma16816(acc[mf][nf], alf[mf], bhf[nf >> 1][2 * (nf & 1)], bhf[nf >> 1][2 * (nf & 1) + 1]);
        }
    };

    auto run = [&](const bf* Ahp, const bf* Alp, long sA, int lda,
                   const bf* Bhp, const bf* Blp, long sB, int ldb, int K, bool first) {
        const bf* Ah = Ahp + z * sA + (long)bm * lda;
        const bf* Al = Alp + z * sA + (long)bm * lda;
        const bf* Bh = Bhp + z * sB + (long)bn * ldb;
        const bf* Bl = Blp + z * sB + (long)bn * ldb;
        const int nch = K >> 5;
        if (!first) __syncthreads();    // protect stage buffers across runs
        load(Ah, Al, lda, Bh, Bl, ldb, 0, 0); CP_COMMIT();
        if (nch > 1) { load(Ah, Al, lda, Bh, Bl, ldb, 1, 1); CP_COMMIT(); }
        for (int c = 0; c < nch; c++) {
            if (c + 1 < nch) cp_wait<1>(); else cp_wait<0>();
            __syncthreads();
            if (c + 2 < nch) {
                load(Ah, Al, lda, Bh, Bl, ldb, c + 2, (c + 2) % 3);
                CP_COMMIT();
            }
            compute(c % 3);
        }
    };

    run(A1h, A1l, sA1, lda1, B1h, B1l, sB1, ldb1, K1, true);
    if (K2 > 0) run(A2h, A2l, sA2, lda2, B2h, B2l, sB2, ldb2, K2, false);

    // epilogue
    const long rbase = z * sC;
#pragma unroll
    for (int mf = 0; mf < 4; mf++) {
#pragma unroll
        for (int nf = 0; nf < 4; nf++) {
            float* d = acc[mf][nf];
            int r = bm + wm * 64 + mf * 16 + (lane >> 2);
            int c = bn + wn * 32 + nf * 8 + (lane & 3) * 2;
            long i0 = rbase + (long)r * ldc + c;
            long i1 = i0 + 8L * ldc;
            if (MODE == 0) {
                float* C = (float*)Chv;
                *(float2*)(C + i0) = make_float2(d[0], d[1]);
                *(float2*)(C + i1) = make_float2(d[2], d[3]);
            } else {
                float v0 = d[0], v1 = d[1], v2 = d[2], v3 = d[3];
                if (MODE == 2) {
                    if (c     > r)     v0 = 0.0f;
                    if (c + 1 > r)     v1 = 0.0f;
                    if (c     > r + 8) v2 = 0.0f;
                    if (c + 1 > r + 8) v3 = 0.0f;
                }
                uint32_t hi0, lo0, hi1, lo1;
                split2(v0, v1, hi0, lo0);
                split2(v2, v3, hi1, lo1);
                bf* Ch = (bf*)Chv; bf* Cl = (bf*)Clv;
                *(uint32_t*)(Ch + i0) = hi0;
                *(uint32_t*)(Cl + i0) = lo0;
                *(uint32_t*)(Ch + i1) = hi1;
                *(uint32_t*)(Cl + i1) = lo1;
            }
        }
    }
}

template <int MODE>
__global__ __launch_bounds__(256, 2)
void gemm2(const bf* __restrict__ A1h, const bf* __restrict__ A1l, long sA1, int lda1,
           const bf* __restrict__ B1h, const bf* __restrict__ B1l, long sB1, int ldb1, int K1,
           const bf* __restrict__ A2h, const bf* __restrict__ A2l, long sA2, int lda2,
           const bf* __restrict__ B2h, const bf* __restrict__ B2l, long sB2, int ldb2, int K2,
           void* __restrict__ Chv, void* __restrict__ Clv, long sC, int ldc)
{
    extern __shared__ __align__(128) char dsm[];
    gemm_core<MODE>(A1h, A1l, sA1, lda1, B1h, B1l, sB1, ldb1, K1,
                    A2h, A2l, sA2, lda2, B2h, B2l, sB2, ldb2, K2,
                    Chv, Clv, sC, ldc,
                    smem_u32(dsm), blockIdx.y * 128, blockIdx.x * 128, blockIdx.z);
}

// ---------------------------------------------------------------------------
// fused scores GEMM (ids 0..255) + k/v transpose (ids 256..16639)
// ---------------------------------------------------------------------------
__global__ __launch_bounds__(256, 2)
void fused_su(const bf* __restrict__ qkvh, const bf* __restrict__ qkvl,
              bf* __restrict__ sch, bf* __restrict__ scl,
              bf* __restrict__ kth, bf* __restrict__ ktl,
              bf* __restrict__ vth, bf* __restrict__ vtl)
{
    extern __shared__ __align__(128) char dsm[];
    const int id = blockIdx.x;
    const int tid = threadIdx.x;

    if (id < 256) {
        // scores block: grid decode (x=n, y=m, z=chunk)
        const int x = id & 1, y = (id >> 1) & 1;
        const long z = id >> 2;
        const int bm = y * 128, bn = x * 128;
        if (bn > bm) {
            // fully above diagonal -> zeros, no compute
            bf* Ch = sch + z * SSQ;
            bf* Cl = scl + z * SSQ;
            const uint4 zz = make_uint4(0u, 0u, 0u, 0u);
            for (int i = tid; i < 2048; i += 256) {
                int r = i >> 4, q = i & 15;
                long off = (long)r * CCHUNK + 128 + q * 8;
                *(uint4*)(Ch + off) = zz;
                *(uint4*)(Cl + off) = zz;
            }
            return;
        }
        gemm_core<2>(qkvh, qkvl, CHQ, 3 * DIMD,
                     qkvh + DIMD, qkvl + DIMD, CHQ, 3 * DIMD, DIMD,
                     nullptr, nullptr, 0, 0, nullptr, nullptr, 0, 0, 0,
                     sch, scl, SSQ, CCHUNK,
                     smem_u32(dsm), bm, bn, z);
    } else {
        // transpose tile: decode (x 0..15, y 0..511, zc 0..1)
        const int t = id - 256;
        const int x = t & 15, y = (t >> 4) & 511, zc = t >> 13;
        bf (*sh)[33] = (bf(*)[33])dsm;
        bf (*sl)[33] = (bf(*)[33])(dsm + 32 * 33 * sizeof(bf));
        const int lds = 3 * DIMD;
        const bf* ih = qkvh + (zc + 1) * DIMD;
        const bf* il = qkvl + (zc + 1) * DIMD;
        bf* oh = zc ? vth : kth;
        bf* ol = zc ? vtl : ktl;
        int c0 = x * 32, r0 = y * 32;
        int tx = tid & 31, ty = tid >> 5;
#pragma unroll
        for (int i = 0; i < 4; i++) {
            long src = (long)(r0 + ty + 8 * i) * lds + c0 + tx;
            sh[ty + 8 * i][tx] = ih[src];
            sl[ty + 8 * i][tx] = il[src];
        }
        __syncthreads();
#pragma unroll
        for (int i = 0; i < 4; i++) {
            long dst = (long)(c0 + ty + 8 * i) * ROWS_TOTAL + r0 + tx;
            oh[dst] = sh[tx][ty + 8 * i];
            ol[dst] = sl[tx][ty + 8 * i];
        }
    }
}

// ---------------------------------------------------------------------------
// fused prep: weight transpose+split (ids 0..1023) + x pack (ids 1024..5119)
// ---------------------------------------------------------------------------
__global__ __launch_bounds__(256)
void prep(const float4* __restrict__ x4, bf* __restrict__ xh, bf* __restrict__ xl, int n4,
          const float* __restrict__ w0, const float* __restrict__ w1,
          const float* __restrict__ w2, const float* __restrict__ w3,
          bf* __restrict__ th, bf* __restrict__ tl)
{
    const int id = blockIdx.x;
    if (id < 1024) {
        const float* Ws[4] = {w0, w1, w2, w3};
        const int wx = id & 15, wy = (id >> 4) & 15, wz = id >> 8;
        const float* W = Ws[wz];
        __shared__ float s[32][33];
        int n0 = wx * 32, k0 = wy * 32;
        int tx = threadIdx.x & 31, ty = threadIdx.x >> 5;
#pragma unroll
        for (int i = 0; i < 4; i++)
            s[ty + 8 * i][tx] = W[(long)(k0 + ty + 8 * i) * DIMD + n0 + tx];
        __syncthreads();
#pragma unroll
        for (int i = 0; i < 4; i++) {
            float v = s[tx][ty + 8 * i];
            uint16_t h, l;
            split1(v, h, l);
            size_t o = (size_t)wz * DIMD * DIMD + (size_t)(n0 + ty + 8 * i) * DIMD + k0 + tx;
            ((uint16_t*)th)[o] = h;
            ((uint16_t*)tl)[o] = l;
        }
    } else {
        const int idp = id - 1024;
        for (int i = idp * 256 + threadIdx.x; i < n4; i += 4096 * 256) {
            float4 f = x4[i];
            uint32_t h0, l0, h1, l1;
            split2(f.x, f.y, h0, l0);
            split2(f.z, f.w, h1, l1);
            *(uint2*)(xh + (size_t)i * 4) = make_uint2(h0, h1);
            *(uint2*)(xl + (size_t)i * 4) = make_uint2(l0, l1);
        }
    }
}

__global__ __launch_bounds__(256)
void prefix_split(const float* __restrict__ st, bf* __restrict__ ph, bf* __restrict__ pl)
{
    const int e = blockIdx.x * 256 + threadIdx.x;
    const int b = blockIdx.y;
    float run = 0.0f;
    for (int c = 0; c < CHUNKS_PER_BATCH; c++) {
        size_t idx = ((size_t)(b * CHUNKS_PER_BATCH + c)) * ((size_t)DIMD * DIMD) + e;
        uint16_t h, l;
        split1(run, h, l);
        ((uint16_t*)ph)[idx] = h;
        ((uint16_t*)pl)[idx] = l;
        run += st[idx];
    }
}

// ---------------------------------------------------------------------------
// launcher
// ---------------------------------------------------------------------------
extern "C" void kernel_launch(void* const* d_in, const int* in_sizes, int n_in,
                              void* d_out, int out_size)
{
    int xi = 0;
    for (int i = 0; i < n_in; i++)
        if (in_sizes[i] == (int)(ROWS_TOTAL * DIMD)) { xi = i; break; }
    const float* W[4]; int wi = 0;
    for (int i = 0; i < n_in && wi < 4; i++) { if (i == xi) continue; W[wi++] = (const float*)d_in[i]; }
    const float* x = (const float*)d_in[xi];

    bf *xh, *xl, *qkvh, *qkvl, *yh, *yl, *kth, *ktl, *vth, *vtl, *wth, *wtl, *ph, *pl, *sch, *scl;
    float *st;
    cudaGetSymbolAddress((void**)&xh, g_xh);     cudaGetSymbolAddress((void**)&xl, g_xl);
    cudaGetSymbolAddress((void**)&qkvh, g_qkvh); cudaGetSymbolAddress((void**)&qkvl, g_qkvl);
    cudaGetSymbolAddress((void**)&yh, g_yh);     cudaGetSymbolAddress((void**)&yl, g_yl);
    cudaGetSymbolAddress((void**)&kth, g_kth);   cudaGetSymbolAddress((void**)&ktl, g_ktl);
    cudaGetSymbolAddress((void**)&vth, g_vth);   cudaGetSymbolAddress((void**)&vtl, g_vtl);
    cudaGetSymbolAddress((void**)&wth, g_wth);   cudaGetSymbolAddress((void**)&wtl, g_wtl);
    cudaGetSymbolAddress((void**)&ph, g_ph);     cudaGetSymbolAddress((void**)&pl, g_pl);
    cudaGetSymbolAddress((void**)&sch, g_sch);   cudaGetSymbolAddress((void**)&scl, g_scl);
    cudaGetSymbolAddress((void**)&st, g_st);

    cudaFuncSetAttribute(gemm2<0>, cudaFuncAttributeMaxDynamicSharedMemorySize, GSMEM);
    cudaFuncSetAttribute(gemm2<1>, cudaFuncAttributeMaxDynamicSharedMemorySize, GSMEM);
    cudaFuncSetAttribute(fused_su, cudaFuncAttributeMaxDynamicSharedMemorySize, GSMEM);

    // prep: pack x + transpose/split weights (one launch)
    prep<<<5120, 256>>>((const float4*)x, xh, xl, (int)(NE / 4),
                        W[0], W[1], W[2], W[3], wth, wtl);

    // fused q|k|v projection: [16384,1536] = x @ [Wq|Wk|Wv]
    gemm2<1><<<dim3(12, 128, 1), 256, GSMEM>>>(
        xh, xl, 0, DIMD, wth, wtl, 0, DIMD, DIMD,
        nullptr, nullptr, 0, 0, nullptr, nullptr, 0, 0, 0,
        qkvh, qkvl, 0, 3 * DIMD);

    // fused: intra-chunk masked scores + k^T/v^T transposes (one launch)
    fused_su<<<16640, 256, GSMEM>>>(qkvh, qkvl, sch, scl, kth, ktl, vth, vtl);

    // per-chunk state S_c = V_c^T K_c (f32), M=512, N=512, K=256
    gemm2<0><<<dim3(4, 4, NCHUNKS), 256, GSMEM>>>(
        vth, vtl, CCHUNK, ROWS_TOTAL, kth, ktl, CCHUNK, ROWS_TOTAL, CCHUNK,
        nullptr, nullptr, 0, 0, nullptr, nullptr, 0, 0, 0,
        st, nullptr, STQ, DIMD);

    // exclusive prefix over chunks -> P planes
    prefix_split<<<dim3((unsigned)(STQ / 256), 4), 256>>>(st, ph, pl);

    // fused Y_c = Q_c @ P_c^T + scores_c @ V_c  -> split planes
    gemm2<1><<<dim3(4, 2, NCHUNKS), 256, GSMEM>>>(
        qkvh, qkvl, CHQ, 3 * DIMD, ph, pl, STQ, DIMD, DIMD,
        sch, scl, SSQ, CCHUNK, vth, vtl, CCHUNK, ROWS_TOTAL, CCHUNK,
        yh, yl, CHY, DIMD);

    // out = Y @ Wo (f32)
    gemm2<0><<<dim3(4, 128, 1), 256, GSMEM>>>(
        yh, yl, 0, DIMD, wth + 3 * STQ, wtl + 3 * STQ, 0, DIMD, DIMD,
        nullptr, nullptr, 0, 0, nullptr, nullptr, 0, 0, 0,
        d_out, nullptr, 0, DIMD);
}

// round 13
// speedup vs baseline: 1.0636x; 1.0636x over previous
#include <cuda_runtime.h>
#include <cuda_bf16.h>
#include <cstdint>
#include <cstddef>

// Problem constants: B=4, S=4096, D=512
#define ROWS_TOTAL 16384
#define DIMD 512
#define CCHUNK 256
#define NCHUNKS 64
#define CHUNKS_PER_BATCH 16

#define NE  ((size_t)ROWS_TOTAL * DIMD)             // 8,388,608
#define NQKV ((size_t)ROWS_TOTAL * 3 * DIMD)        // 25,165,824
#define STN ((size_t)NCHUNKS * DIMD * DIMD)         // 16,777,216
#define SCN ((size_t)NCHUNKS * CCHUNK * CCHUNK)     // 4,194,304

#define SSQ ((long)CCHUNK * CCHUNK)                 // 65536
#define CHQ ((long)CCHUNK * 3 * DIMD)               // 393216
#define CHY ((long)CCHUNK * DIMD)                   // 131072
#define STQ ((long)DIMD * DIMD)                     // 262144

typedef __nv_bfloat16 bf;

// ---------------------------------------------------------------------------
// Scratch (static device globals)
// ---------------------------------------------------------------------------
__device__ __align__(16) bf g_xh[NE], g_xl[NE];
__device__ __align__(16) bf g_qkvh[NQKV], g_qkvl[NQKV];     // [16384][1536]
__device__ __align__(16) bf g_yh[NE], g_yl[NE];
__device__ __align__(16) bf g_kth[NE], g_ktl[NE];           // [512][16384]
__device__ __align__(16) bf g_vth[NE], g_vtl[NE];
__device__ __align__(16) bf g_wth[(size_t)4 * DIMD * DIMD]; // [4][512 n][512 k] = W^T
__device__ __align__(16) bf g_wtl[(size_t)4 * DIMD * DIMD];
__device__ __align__(16) bf g_ph[STN], g_pl[STN];
__device__ __align__(16) bf g_sch[SCN], g_scl[SCN];
__device__ __align__(16) float g_st[STN];

// ---------------------------------------------------------------------------
// helpers
// ---------------------------------------------------------------------------
__device__ __forceinline__ uint32_t smem_u32(const void* p) {
    uint32_t a;
    asm("{ .reg .u64 t; cvta.to.shared.u64 t, %1; cvt.u32.u64 %0, t; }" : "=r"(a) : "l"(p));
    return a;
}
__device__ __forceinline__ void cp16(uint32_t dst, const void* src) {
    asm volatile("cp.async.cg.shared.global [%0], [%1], 16;" :: "r"(dst), "l"(src));
}
#define CP_COMMIT() asm volatile("cp.async.commit_group;" ::: "memory")
template <int N> __device__ __forceinline__ void cp_wait() {
    asm volatile("cp.async.wait_group %0;" :: "n"(N) : "memory");
}
__device__ __forceinline__ void ldm4(uint32_t* r, uint32_t addr) {
    asm volatile("ldmatrix.sync.aligned.m8n8.x4.shared.b16 {%0,%1,%2,%3}, [%4];"
                 : "=r"(r[0]), "=r"(r[1]), "=r"(r[2]), "=r"(r[3]) : "r"(addr));
}
__device__ __forceinline__ void mma16816(float* d, const uint32_t* a, uint32_t b0, uint32_t b1) {
    asm volatile("mma.sync.aligned.m16n8k16.row.col.f32.bf16.bf16.f32 "
                 "{%0,%1,%2,%3},{%4,%5,%6,%7},{%8,%9},{%0,%1,%2,%3};"
                 : "+f"(d[0]), "+f"(d[1]), "+f"(d[2]), "+f"(d[3])
                 : "r"(a[0]), "r"(a[1]), "r"(a[2]), "r"(a[3]), "r"(b0), "r"(b1));
}
__device__ __forceinline__ void split1(float v, uint16_t& h, uint16_t& l) {
    __nv_bfloat16 hb = __float2bfloat16(v);
    __nv_bfloat16 lb = __float2bfloat16(v - __bfloat162float(hb));
    h = __bfloat16_as_ushort(hb);
    l = __bfloat16_as_ushort(lb);
}
__device__ __forceinline__ void split2(float v0, float v1, uint32_t& hi, uint32_t& lo) {
    uint16_t h0, l0, h1, l1;
    split1(v0, h0, l0); split1(v1, h1, l1);
    hi = (uint32_t)h0 | ((uint32_t)h1 << 16);
    lo = (uint32_t)l0 | ((uint32_t)l1 << 16);
}

// ---------------------------------------------------------------------------
// shared GEMM core: CTA tile 128x128, 4 warps (2m x 2n), warp tile 64x64.
// C = sum_k A1*B1^T (+ sum_k A2*B2^T if K2>0), split-bf16 3-term, fp32 accum.
// 3-stage cp.async pipeline, one __syncthreads per 32-k chunk, 2 CTAs/SM.
// Halved LDSM bytes/MMA vs 64x32 warp tile (A and B frags reused 2x wider).
// MODE 0: C f32; MODE 1: split planes; MODE 2: split planes + causal mask.
// ---------------------------------------------------------------------------
#define NTHR 128
#define STAGE_BYTES 32768
#define GSMEM (3 * STAGE_BYTES)   // 96 KB -> 2 CTAs/SM

template <int MODE>
__device__ __forceinline__ void gemm_core(
    const bf* __restrict__ A1h, const bf* __restrict__ A1l, long sA1, int lda1,
    const bf* __restrict__ B1h, const bf* __restrict__ B1l, long sB1, int ldb1, int K1,
    const bf* __restrict__ A2h, const bf* __restrict__ A2l, long sA2, int lda2,
    const bf* __restrict__ B2h, const bf* __restrict__ B2l, long sB2, int ldb2, int K2,
    void* __restrict__ Chv, void* __restrict__ Clv, long sC, int ldc,
    uint32_t sm, int bm, int bn, long z)
{
    const int tid = threadIdx.x, lane = tid & 31, wid = tid >> 5;
    const int wm = wid & 1, wn = (wid >> 1) & 1;      // 2 x 2

    float acc[4][8][4];
#pragma unroll
    for (int i = 0; i < 4; i++)
#pragma unroll
        for (int j = 0; j < 8; j++)
#pragma unroll
            for (int q = 0; q < 4; q++) acc[i][j][q] = 0.0f;

    auto load = [&](const bf* Ah, const bf* Al, int lda,
                    const bf* Bh, const bf* Bl, int ldb, int c, int buf) {
        const int k0 = c * 32;
        const uint32_t sb = sm + buf * STAGE_BYTES;
#pragma unroll
        for (int i = 0; i < 8; i++) {
            int e = tid + NTHR * i;             // A: 1024 cp16
            int row = e >> 3, ch = e & 7;
            int kc = k0 + (ch & 3) * 8;
            const bf* src = (ch < 4 ? Ah : Al) + (long)row * lda + kc;
            uint32_t sw = (uint32_t)(row * 128 + ((ch ^ (row & 7)) << 4));
            cp16(sb + sw, src);
        }
#pragma unroll
        for (int i = 0; i < 8; i++) {
            int e = tid + NTHR * i;             // B: 1024 cp16
            int row = e >> 3, ch = e & 7;
            int kc = k0 + (ch & 3) * 8;
            const bf* src = (ch < 4 ? Bh : Bl) + (long)row * ldb + kc;
            uint32_t sw = (uint32_t)(row * 128 + ((ch ^ (row & 7)) << 4));
            cp16(sb + 16384 + sw, src);
        }
    };

    auto compute = [&](int buf) {
        const uint32_t ba = sm + buf * STAGE_BYTES;
        const uint32_t bb = ba + 16384;
#pragma unroll
        for (int kh2 = 0; kh2 < 2; kh2++) {
            uint32_t ahf[4][4], alf[4][4], bhf[4][4], blf[4][4];
            // ---- ldsm burst: 8 A + 8 B, all independent ----
            {
                int arow = wm * 64 + (lane & 7) + ((lane >> 3) & 1) * 8;
                int ach = kh2 * 2 + (lane >> 4);
#pragma unroll
                for (int mf = 0; mf < 4; mf++) {
                    int row = arow + mf * 16;
                    ldm4(ahf[mf], ba + row * 128 + ((ach ^ (row & 7)) << 4));
                }
#pragma unroll
                for (int mf = 0; mf < 4; mf++) {
                    int row = arow + mf * 16;
                    ldm4(alf[mf], ba + row * 128 + (((ach + 4) ^ (row & 7)) << 4));
                }
                int brow = wn * 64 + (lane & 7) + (lane >> 4) * 8;
                int bch = kh2 * 2 + ((lane >> 3) & 1);
#pragma unroll
                for (int bi = 0; bi < 4; bi++) {
                    int row = brow + bi * 16;
                    ldm4(bhf[bi], bb + row * 128 + ((bch ^ (row & 7)) << 4));
                }
#pragma unroll
                for (int bi = 0; bi < 4; bi++) {
                    int row = brow + bi * 16;
                    ldm4(blf[bi], bb + row * 128 + (((bch + 4) ^ (row & 7)) << 4));
                }
            }
            // ---- 96 MMAs, term-major; per-acc order hh, hl, lh ----
#pragma unroll
            for (int mf = 0; mf < 4; mf++)
#pragma unroll
                for (int nf = 0; nf < 8; nf++)
                    mma16816(acc[mf][nf], ahf[mf], bhf[nf >> 1][2 * (nf & 1)], bhf[nf >> 1][2 * (nf & 1) + 1]);
#pragma unroll
            for (int mf = 0; mf < 4; mf++)
#pragma unroll
                for (int nf = 0; nf < 8; nf++)
                    mma16816(acc[mf][nf], ahf[mf], blf[nf >> 1][2 * (nf & 1)], blf[nf >> 1][2 * (nf & 1) + 1]);
#pragma unroll
            for (int mf = 0; mf < 4; mf++)
#pragma unroll
                for (int nf = 0; nf < 8; nf++)
                    mma16816(acc[mf][nf], alf[mf], bhf[nf >> 1][2 * (nf & 1)], bhf[nf >> 1][2 * (nf & 1) + 1]);
        }
    };

    auto run = [&](const bf* Ahp, const bf* Alp, long sA, int lda,
                   const bf* Bhp, const bf* Blp, long sB, int ldb, int K, bool first) {
        const bf* Ah = Ahp + z * sA + (long)bm * lda;
        const bf* Al = Alp + z * sA + (long)bm * lda;
        const bf* Bh = Bhp + z * sB + (long)bn * ldb;
        const bf* Bl = Blp + z * sB + (long)bn * ldb;
        const int nch = K >> 5;
        if (!first) __syncthreads();    // protect stage buffers across runs
        load(Ah, Al, lda, Bh, Bl, ldb, 0, 0); CP_COMMIT();
        if (nch > 1) { load(Ah, Al, lda, Bh, Bl, ldb, 1, 1); CP_COMMIT(); }
        for (int c = 0; c < nch; c++) {
            if (c + 1 < nch) cp_wait<1>(); else cp_wait<0>();
            __syncthreads();
            if (c + 2 < nch) {
                load(Ah, Al, lda, Bh, Bl, ldb, c + 2, (c + 2) % 3);
                CP_COMMIT();
            }
            compute(c % 3);
        }
    };

    run(A1h, A1l, sA1, lda1, B1h, B1l, sB1, ldb1, K1, true);
    if (K2 > 0) run(A2h, A2l, sA2, lda2, B2h, B2l, sB2, ldb2, K2, false);

    // epilogue
    const long rbase = z * sC;
#pragma unroll
    for (int mf = 0; mf < 4; mf++) {
#pragma unroll
        for (int nf = 0; nf < 8; nf++) {
            float* d = acc[mf][nf];
            int r = bm + wm * 64 + mf * 16 + (lane >> 2);
            int c = bn + wn * 64 + nf * 8 + (lane & 3) * 2;
            long i0 = rbase + (long)r * ldc + c;
            long i1 = i0 + 8L * ldc;
            if (MODE == 0) {
                float* C = (float*)Chv;
                *(float2*)(C + i0) = make_float2(d[0], d[1]);
                *(float2*)(C + i1) = make_float2(d[2], d[3]);
            } else {
                float v0 = d[0], v1 = d[1], v2 = d[2], v3 = d[3];
                if (MODE == 2) {
                    if (c     > r)     v0 = 0.0f;
                    if (c + 1 > r)     v1 = 0.0f;
                    if (c     > r + 8) v2 = 0.0f;
                    if (c + 1 > r + 8) v3 = 0.0f;
                }
                uint32_t hi0, lo0, hi1, lo1;
                split2(v0, v1, hi0, lo0);
                split2(v2, v3, hi1, lo1);
                bf* Ch = (bf*)Chv; bf* Cl = (bf*)Clv;
                *(uint32_t*)(Ch + i0) = hi0;
                *(uint32_t*)(Cl + i0) = lo0;
                *(uint32_t*)(Ch + i1) = hi1;
                *(uint32_t*)(Cl + i1) = lo1;
            }
        }
    }
}

template <int MODE>
__global__ __launch_bounds__(NTHR, 2)
void gemm2(const bf* __restrict__ A1h, const bf* __restrict__ A1l, long sA1, int lda1,
           const bf* __restrict__ B1h, const bf* __restrict__ B1l, long sB1, int ldb1, int K1,
           const bf* __restrict__ A2h, const bf* __restrict__ A2l, long sA2, int lda2,
           const bf* __restrict__ B2h, const bf* __restrict__ B2l, long sB2, int ldb2, int K2,
           void* __restrict__ Chv, void* __restrict__ Clv, long sC, int ldc)
{
    extern __shared__ __align__(128) char dsm[];
    gemm_core<MODE>(A1h, A1l, sA1, lda1, B1h, B1l, sB1, ldb1, K1,
                    A2h, A2l, sA2, lda2, B2h, B2l, sB2, ldb2, K2,
                    Chv, Clv, sC, ldc,
                    smem_u32(dsm), blockIdx.y * 128, blockIdx.x * 128, blockIdx.z);
}

// ---------------------------------------------------------------------------
// fused scores GEMM (ids 0..255) + k/v transpose (ids 256..8447, 2 tiles each)
// ---------------------------------------------------------------------------
__global__ __launch_bounds__(NTHR, 2)
void fused_su(const bf* __restrict__ qkvh, const bf* __restrict__ qkvl,
              bf* __restrict__ sch, bf* __restrict__ scl,
              bf* __restrict__ kth, bf* __restrict__ ktl,
              bf* __restrict__ vth, bf* __restrict__ vtl)
{
    extern __shared__ __align__(128) char dsm[];
    const int id = blockIdx.x;
    const int tid = threadIdx.x;

    if (id < 256) {
        // scores block: grid decode (x=n, y=m, z=chunk)
        const int x = id & 1, y = (id >> 1) & 1;
        const long z = id >> 2;
        const int bm = y * 128, bn = x * 128;
        if (bn > bm) {
            // fully above diagonal -> zeros, no compute
            bf* Ch = sch + z * SSQ;
            bf* Cl = scl + z * SSQ;
            const uint4 zz = make_uint4(0u, 0u, 0u, 0u);
            for (int i = tid; i < 2048; i += NTHR) {
                int r = i >> 4, q = i & 15;
                long off = (long)r * CCHUNK + 128 + q * 8;
                *(uint4*)(Ch + off) = zz;
                *(uint4*)(Cl + off) = zz;
            }
            return;
        }
        gemm_core<2>(qkvh, qkvl, CHQ, 3 * DIMD,
                     qkvh + DIMD, qkvl + DIMD, CHQ, 3 * DIMD, DIMD,
                     nullptr, nullptr, 0, 0, nullptr, nullptr, 0, 0, 0,
                     sch, scl, SSQ, CCHUNK,
                     smem_u32(dsm), bm, bn, z);
    } else {
        // transpose: each CTA handles 2 tiles; tt decode (x 0..15, y 0..511, zc 0..1)
        bf (*sh)[33] = (bf(*)[33])dsm;
        bf (*sl)[33] = (bf(*)[33])(dsm + 32 * 33 * sizeof(bf));
        const int lds = 3 * DIMD;
        const int tx = tid & 31, ty = tid >> 5;   // ty 0..3
        const int base = (id - 256) * 2;
#pragma unroll
        for (int sub = 0; sub < 2; sub++) {
            const int tt = base + sub;
            const int x = tt & 15, y = (tt >> 4) & 511, zc = tt >> 13;
            const bf* ih = qkvh + (zc + 1) * DIMD;
            const bf* il = qkvl + (zc + 1) * DIMD;
            bf* oh = zc ? vth : kth;
            bf* ol = zc ? vtl : ktl;
            int c0 = x * 32, r0 = y * 32;
            if (sub) __syncthreads();
#pragma unroll
            for (int i = 0; i < 8; i++) {
                long src = (long)(r0 + ty + 4 * i) * lds + c0 + tx;
                sh[ty + 4 * i][tx] = ih[src];
                sl[ty + 4 * i][tx] = il[src];
            }
            __syncthreads();
#pragma unroll
            for (int i = 0; i < 8; i++) {
                long dst = (long)(c0 + ty + 4 * i) * ROWS_TOTAL + r0 + tx;
                oh[dst] = sh[tx][ty + 4 * i];
                ol[dst] = sl[tx][ty + 4 * i];
            }
        }
    }
}

// ---------------------------------------------------------------------------
// fused prep: weight transpose+split (ids 0..1023) + x pack (ids 1024..5119)
// ---------------------------------------------------------------------------
__global__ __launch_bounds__(256)
void prep(const float4* __restrict__ x4, bf* __restrict__ xh, bf* __restrict__ xl, int n4,
          const float* __restrict__ w0, const float* __restrict__ w1,
          const float* __restrict__ w2, const float* __restrict__ w3,
          bf* __restrict__ th, bf* __restrict__ tl)
{
    const int id = blockIdx.x;
    if (id < 1024) {
        const float* Ws[4] = {w0, w1, w2, w3};
        const int wx = id & 15, wy = (id >> 4) & 15, wz = id >> 8;
        const float* W = Ws[wz];
        __shared__ float s[32][33];
        int n0 = wx * 32, k0 = wy * 32;
        int tx = threadIdx.x & 31, ty = threadIdx.x >> 5;
#pragma unroll
        for (int i = 0; i < 4; i++)
            s[ty + 8 * i][tx] = W[(long)(k0 + ty + 8 * i) * DIMD + n0 + tx];
        __syncthreads();
#pragma unroll
        for (int i = 0; i < 4; i++) {
            float v = s[tx][ty + 8 * i];
            uint16_t h, l;
            split1(v, h, l);
            size_t o = (size_t)wz * DIMD * DIMD + (size_t)(n0 + ty + 8 * i) * DIMD + k0 + tx;
            ((uint16_t*)th)[o] = h;
            ((uint16_t*)tl)[o] = l;
        }
    } else {
        const int idp = id - 1024;
        for (int i = idp * 256 + threadIdx.x; i < n4; i += 4096 * 256) {
            float4 f = x4[i];
            uint32_t h0, l0, h1, l1;
            split2(f.x, f.y, h0, l0);
            split2(f.z, f.w, h1, l1);
            *(uint2*)(xh + (size_t)i * 4) = make_uint2(h0, h1);
            *(uint2*)(xl + (size_t)i * 4) = make_uint2(l0, l1);
        }
    }
}

__global__ __launch_bounds__(256)
void prefix_split(const float* __restrict__ st, bf* __restrict__ ph, bf* __restrict__ pl)
{
    const int e = blockIdx.x * 256 + threadIdx.x;
    const int b = blockIdx.y;
    float run = 0.0f;
    for (int c = 0; c < CHUNKS_PER_BATCH; c++) {
        size_t idx = ((size_t)(b * CHUNKS_PER_BATCH + c)) * ((size_t)DIMD * DIMD) + e;
        uint16_t h, l;
        split1(run, h, l);
        ((uint16_t*)ph)[idx] = h;
        ((uint16_t*)pl)[idx] = l;
        run += st[idx];
    }
}

// ---------------------------------------------------------------------------
// launcher
// ---------------------------------------------------------------------------
extern "C" void kernel_launch(void* const* d_in, const int* in_sizes, int n_in,
                              void* d_out, int out_size)
{
    int xi = 0;
    for (int i = 0; i < n_in; i++)
        if (in_sizes[i] == (int)(ROWS_TOTAL * DIMD)) { xi = i; break; }
    const float* W[4]; int wi = 0;
    for (int i = 0; i < n_in && wi < 4; i++) { if (i == xi) continue; W[wi++] = (const float*)d_in[i]; }
    const float* x = (const float*)d_in[xi];

    bf *xh, *xl, *qkvh, *qkvl, *yh, *yl, *kth, *ktl, *vth, *vtl, *wth, *wtl, *ph, *pl, *sch, *scl;
    float *st;
    cudaGetSymbolAddress((void**)&xh, g_xh);     cudaGetSymbolAddress((void**)&xl, g_xl);
    cudaGetSymbolAddress((void**)&qkvh, g_qkvh); cudaGetSymbolAddress((void**)&qkvl, g_qkvl);
    cudaGetSymbolAddress((void**)&yh, g_yh);     cudaGetSymbolAddress((void**)&yl, g_yl);
    cudaGetSymbolAddress((void**)&kth, g_kth);   cudaGetSymbolAddress((void**)&ktl, g_ktl);
    cudaGetSymbolAddress((void**)&vth, g_vth);   cudaGetSymbolAddress((void**)&vtl, g_vtl);
    cudaGetSymbolAddress((void**)&wth, g_wth);   cudaGetSymbolAddress((void**)&wtl, g_wtl);
    cudaGetSymbolAddress((void**)&ph, g_ph);     cudaGetSymbolAddress((void**)&pl, g_pl);
    cudaGetSymbolAddress((void**)&sch, g_sch);   cudaGetSymbolAddress((void**)&scl, g_scl);
    cudaGetSymbolAddress((void**)&st, g_st);

    cudaFuncSetAttribute(gemm2<0>, cudaFuncAttributeMaxDynamicSharedMemorySize, GSMEM);
    cudaFuncSetAttribute(gemm2<1>, cudaFuncAttributeMaxDynamicSharedMemorySize, GSMEM);
    cudaFuncSetAttribute(fused_su, cudaFuncAttributeMaxDynamicSharedMemorySize, GSMEM);

    // prep: pack x + transpose/split weights (one launch)
    prep<<<5120, 256>>>((const float4*)x, xh, xl, (int)(NE / 4),
                        W[0], W[1], W[2], W[3], wth, wtl);

    // fused q|k|v projection: [16384,1536] = x @ [Wq|Wk|Wv]
    gemm2<1><<<dim3(12, 128, 1), NTHR, GSMEM>>>(
        xh, xl, 0, DIMD, wth, wtl, 0, DIMD, DIMD,
        nullptr, nullptr, 0, 0, nullptr, nullptr, 0, 0, 0,
        qkvh, qkvl, 0, 3 * DIMD);

    // fused: intra-chunk masked scores + k^T/v^T transposes (one launch)
    fused_su<<<8448, NTHR, GSMEM>>>(qkvh, qkvl, sch, scl, kth, ktl, vth, vtl);

    // per-chunk state S_c = V_c^T K_c (f32), M=512, N=512, K=256
    gemm2<0><<<dim3(4, 4, NCHUNKS), NTHR, GSMEM>>>(
        vth, vtl, CCHUNK, ROWS_TOTAL, kth, ktl, CCHUNK, ROWS_TOTAL, CCHUNK,
        nullptr, nullptr, 0, 0, nullptr, nullptr, 0, 0, 0,
        st, nullptr, STQ, DIMD);

    // exclusive prefix over chunks -> P planes
    prefix_split<<<dim3((unsigned)(STQ / 256), 4), 256>>>(st, ph, pl);

    // fused Y_c = Q_c @ P_c^T + scores_c @ V_c  -> split planes
    gemm2<1><<<dim3(4, 2, NCHUNKS), NTHR, GSMEM>>>(
        qkvh, qkvl, CHQ, 3 * DIMD, ph, pl, STQ, DIMD, DIMD,
        sch, scl, SSQ, CCHUNK, vth, vtl, CCHUNK, ROWS_TOTAL, CCHUNK,
        yh, yl, CHY, DIMD);

    // out = Y @ Wo (f32)
    gemm2<0><<<dim3(4, 128, 1), NTHR, GSMEM>>>(
        yh, yl, 0, DIMD, wth + 3 * STQ, wtl + 3 * STQ, 0, DIMD, DIMD,
        nullptr, nullptr, 0, 0, nullptr, nullptr, 0, 0, 0,
        d_out, nullptr, 0, DIMD);
}

// round 14
// speedup vs baseline: 1.1496x; 1.0809x over previous
#include <cuda_runtime.h>
#include <cuda_bf16.h>
#include <cstdint>
#include <cstddef>

// Problem constants: B=4, S=4096, D=512
#define ROWS_TOTAL 16384
#define DIMD 512
#define CCHUNK 256
#define NCHUNKS 64
#define CHUNKS_PER_BATCH 16

#define NE  ((size_t)ROWS_TOTAL * DIMD)             // 8,388,608
#define NQKV ((size_t)ROWS_TOTAL * 3 * DIMD)        // 25,165,824
#define STN ((size_t)NCHUNKS * DIMD * DIMD)         // 16,777,216
#define SCN ((size_t)NCHUNKS * CCHUNK * CCHUNK)     // 4,194,304

#define SSQ ((long)CCHUNK * CCHUNK)                 // 65536
#define CHQ ((long)CCHUNK * 3 * DIMD)               // 393216
#define CHY ((long)CCHUNK * DIMD)                   // 131072
#define STQ ((long)DIMD * DIMD)                     // 262144

typedef __nv_bfloat16 bf;

// ---------------------------------------------------------------------------
// Scratch (static device globals)
// ---------------------------------------------------------------------------
__device__ __align__(16) bf g_xh[NE], g_xl[NE];
__device__ __align__(16) bf g_qkvh[NQKV], g_qkvl[NQKV];     // [16384][1536]
__device__ __align__(16) bf g_yh[NE], g_yl[NE];
__device__ __align__(16) bf g_wth[(size_t)4 * DIMD * DIMD]; // [4][512 n][512 k] = W^T
__device__ __align__(16) bf g_wtl[(size_t)4 * DIMD * DIMD];
__device__ __align__(16) bf g_ph[STN], g_pl[STN];
__device__ __align__(16) bf g_sch[SCN], g_scl[SCN];
__device__ __align__(16) float g_st[STN];

// ---------------------------------------------------------------------------
// helpers
// ---------------------------------------------------------------------------
__device__ __forceinline__ uint32_t smem_u32(const void* p) {
    uint32_t a;
    asm("{ .reg .u64 t; cvta.to.shared.u64 t, %1; cvt.u32.u64 %0, t; }" : "=r"(a) : "l"(p));
    return a;
}
__device__ __forceinline__ void cp16(uint32_t dst, const void* src) {
    asm volatile("cp.async.cg.shared.global [%0], [%1], 16;" :: "r"(dst), "l"(src));
}
#define CP_COMMIT() asm volatile("cp.async.commit_group;" ::: "memory")
template <int N> __device__ __forceinline__ void cp_wait() {
    asm volatile("cp.async.wait_group %0;" :: "n"(N) : "memory");
}
__device__ __forceinline__ void ldm4(uint32_t* r, uint32_t addr) {
    asm volatile("ldmatrix.sync.aligned.m8n8.x4.shared.b16 {%0,%1,%2,%3}, [%4];"
                 : "=r"(r[0]), "=r"(r[1]), "=r"(r[2]), "=r"(r[3]) : "r"(addr));
}
__device__ __forceinline__ void ldm4t(uint32_t* r, uint32_t addr) {
    asm volatile("ldmatrix.sync.aligned.m8n8.x4.trans.shared.b16 {%0,%1,%2,%3}, [%4];"
                 : "=r"(r[0]), "=r"(r[1]), "=r"(r[2]), "=r"(r[3]) : "r"(addr));
}
__device__ __forceinline__ void mma16816(float* d, const uint32_t* a, uint32_t b0, uint32_t b1) {
    asm volatile("mma.sync.aligned.m16n8k16.row.col.f32.bf16.bf16.f32 "
                 "{%0,%1,%2,%3},{%4,%5,%6,%7},{%8,%9},{%0,%1,%2,%3};"
                 : "+f"(d[0]), "+f"(d[1]), "+f"(d[2]), "+f"(d[3])
                 : "r"(a[0]), "r"(a[1]), "r"(a[2]), "r"(a[3]), "r"(b0), "r"(b1));
}
__device__ __forceinline__ void split1(float v, uint16_t& h, uint16_t& l) {
    __nv_bfloat16 hb = __float2bfloat16(v);
    __nv_bfloat16 lb = __float2bfloat16(v - __bfloat162float(hb));
    h = __bfloat16_as_ushort(hb);
    l = __bfloat16_as_ushort(lb);
}
__device__ __forceinline__ void split2(float v0, float v1, uint32_t& hi, uint32_t& lo) {
    uint16_t h0, l0, h1, l1;
    split1(v0, h0, l0); split1(v1, h1, l1);
    hi = (uint32_t)h0 | ((uint32_t)h1 << 16);
    lo = (uint32_t)l0 | ((uint32_t)l1 << 16);
}

// ---------------------------------------------------------------------------
// GEMM core: CTA 128x128, 4 warps (2m x 2n), warp tile 64x64, 3-stage pipeline.
// Operand types: T=0 normal (stored [m][k], rows=m); T=1 trans (stored [k][m],
// rows=k(t), loaded via ldmatrix.trans). Same products, same accumulation order.
//
// Normal tile layout (16KB/operand): row m (128) * 128B; chunks 0-3 hi-k-groups,
//   4-7 lo; chunk swizzle ^(row&7).
// Trans tile layout (16KB/operand): plane p*8KB + t(32)*256B + (mg>>3)*128B +
//   (((mg&7)^(t&7))<<4), mg = m/8 (0..15).
// ---------------------------------------------------------------------------
#define NTHR 128
#define STAGE_BYTES 32768
#define GSMEM (3 * STAGE_BYTES)   // 96 KB -> 2 CTAs/SM

template <int TA, int TB>
__device__ __forceinline__ void run_k(
    float (&acc)[4][8][4], uint32_t sm,
    const bf* __restrict__ Ah, const bf* __restrict__ Al, int lda,
    const bf* __restrict__ Bh, const bf* __restrict__ Bl, int ldb,
    int K, bool first, int tid, int lane, int wm, int wn)
{
    auto load = [&](int c, int buf) {
        const int k0 = c * 32;
        const uint32_t sb = sm + buf * STAGE_BYTES;
#pragma unroll
        for (int i = 0; i < 8; i++) {
            int e = tid + NTHR * i;             // A: 1024 cp16
            if (TA == 0) {
                int row = e >> 3, ch = e & 7;
                const bf* src = (ch < 4 ? Ah : Al) + (long)row * lda + k0 + (ch & 3) * 8;
                cp16(sb + (uint32_t)(row * 128 + ((ch ^ (row & 7)) << 4)), src);
            } else {
                int p = e >> 9, t = (e >> 4) & 31, mg = e & 15;
                const bf* src = (p ? Al : Ah) + (long)(k0 + t) * lda + mg * 8;
                cp16(sb + (uint32_t)(p * 8192 + t * 256 + ((mg >> 3) & 1) * 128 +
                                     (((mg & 7) ^ (t & 7)) << 4)), src);
            }
        }
#pragma unroll
        for (int i = 0; i < 8; i++) {
            int e = tid + NTHR * i;             // B: 1024 cp16
            if (TB == 0) {
                int row = e >> 3, ch = e & 7;
                const bf* src = (ch < 4 ? Bh : Bl) + (long)row * ldb + k0 + (ch & 3) * 8;
                cp16(sb + 16384 + (uint32_t)(row * 128 + ((ch ^ (row & 7)) << 4)), src);
            } else {
                int p = e >> 9, t = (e >> 4) & 31, mg = e & 15;
                const bf* src = (p ? Bl : Bh) + (long)(k0 + t) * ldb + mg * 8;
                cp16(sb + 16384 + (uint32_t)(p * 8192 + t * 256 + ((mg >> 3) & 1) * 128 +
                                             (((mg & 7) ^ (t & 7)) << 4)), src);
            }
        }
    };

    auto compute = [&](int buf) {
        const uint32_t ba = sm + buf * STAGE_BYTES;
        const uint32_t bb = ba + 16384;
#pragma unroll
        for (int kh2 = 0; kh2 < 2; kh2++) {
            uint32_t ahf[4][4], alf[4][4], bhf[4][4], blf[4][4];
            // ---- A fragments ----
            if (TA == 0) {
                int arow = wm * 64 + (lane & 7) + ((lane >> 3) & 1) * 8;
                int ach = kh2 * 2 + (lane >> 4);
#pragma unroll
                for (int mf = 0; mf < 4; mf++) {
                    int row = arow + mf * 16;
                    ldm4(ahf[mf], ba + row * 128 + ((ach ^ (row & 7)) << 4));
                }
#pragma unroll
                for (int mf = 0; mf < 4; mf++) {
                    int row = arow + mf * 16;
                    ldm4(alf[mf], ba + row * 128 + (((ach + 4) ^ (row & 7)) << 4));
                }
            } else {
                // matrices: (m0-7,k0-7),(m8-15,k0-7),(m0-7,k8-15),(m8-15,k8-15)
                int t = kh2 * 16 + ((lane >> 4) & 1) * 8 + (lane & 7);
                int mh = (lane >> 3) & 1;
#pragma unroll
                for (int mf = 0; mf < 4; mf++) {
                    int mg = wm * 8 + mf * 2 + mh;
                    uint32_t off = (uint32_t)(t * 256 + ((mg >> 3) & 1) * 128 +
                                              (((mg & 7) ^ (t & 7)) << 4));
                    ldm4t(ahf[mf], ba + off);
                }
#pragma unroll
                for (int mf = 0; mf < 4; mf++) {
                    int mg = wm * 8 + mf * 2 + mh;
                    uint32_t off = (uint32_t)(t * 256 + ((mg >> 3) & 1) * 128 +
                                              (((mg & 7) ^ (t & 7)) << 4));
                    ldm4t(alf[mf], ba + 8192 + off);
                }
            }
            // ---- B fragments ----
            if (TB == 0) {
                int brow = wn * 64 + (lane & 7) + (lane >> 4) * 8;
                int bch = kh2 * 2 + ((lane >> 3) & 1);
#pragma unroll
                for (int bi = 0; bi < 4; bi++) {
                    int row = brow + bi * 16;
                    ldm4(bhf[bi], bb + row * 128 + ((bch ^ (row & 7)) << 4));
                }
#pragma unroll
                for (int bi = 0; bi < 4; bi++) {
                    int row = brow + bi * 16;
                    ldm4(blf[bi], bb + row * 128 + (((bch + 4) ^ (row & 7)) << 4));
                }
            } else {
                // matrices: (n0-7,k0-7),(n0-7,k8-15),(n8-15,k0-7),(n8-15,k8-15)
                int t = kh2 * 16 + ((lane >> 3) & 1) * 8 + (lane & 7);
                int nh = (lane >> 4) & 1;
#pragma unroll
                for (int bi = 0; bi < 4; bi++) {
                    int ng = wn * 8 + bi * 2 + nh;
                    uint32_t off = (uint32_t)(t * 256 + ((ng >> 3) & 1) * 128 +
                                              (((ng & 7) ^ (t & 7)) << 4));
                    ldm4t(bhf[bi], bb + off);
                }
#pragma unroll
                for (int bi = 0; bi < 4; bi++) {
                    int ng = wn * 8 + bi * 2 + nh;
                    uint32_t off = (uint32_t)(t * 256 + ((ng >> 3) & 1) * 128 +
                                              (((ng & 7) ^ (t & 7)) << 4));
                    ldm4t(blf[bi], bb + 8192 + off);
                }
            }
            // ---- 96 MMAs, term-major; per-acc order hh, hl, lh ----
#pragma unroll
            for (int mf = 0; mf < 4; mf++)
#pragma unroll
                for (int nf = 0; nf < 8; nf++)
                    mma16816(acc[mf][nf], ahf[mf], bhf[nf >> 1][2 * (nf & 1)], bhf[nf >> 1][2 * (nf & 1) + 1]);
#pragma unroll
            for (int mf = 0; mf < 4; mf++)
#pragma unroll
                for (int nf = 0; nf < 8; nf++)
                    mma16816(acc[mf][nf], ahf[mf], blf[nf >> 1][2 * (nf & 1)], blf[nf >> 1][2 * (nf & 1) + 1]);
#pragma unroll
            for (int mf = 0; mf < 4; mf++)
#pragma unroll
                for (int nf = 0; nf < 8; nf++)
                    mma16816(acc[mf][nf], alf[mf], bhf[nf >> 1][2 * (nf & 1)], bhf[nf >> 1][2 * (nf & 1) + 1]);
        }
    };

    const int nch = K >> 5;
    if (!first) __syncthreads();
    load(0, 0); CP_COMMIT();
    if (nch > 1) { load(1, 1); CP_COMMIT(); }
    for (int c = 0; c < nch; c++) {
        if (c + 1 < nch) cp_wait<1>(); else cp_wait<0>();
        __syncthreads();
        if (c + 2 < nch) { load(c + 2, (c + 2) % 3); CP_COMMIT(); }
        compute(c % 3);
    }
}

// gemm_core: pointer pre-offsetting per operand type.
// Normal operand: base + z*s + bm*ld (rows = m). Trans: base + z*s + bm (cols = m).
template <int MODE, int TA1, int TB1, int TA2, int TB2>
__device__ __forceinline__ void gemm_core(
    const bf* __restrict__ A1h, const bf* __restrict__ A1l, long sA1, int lda1,
    const bf* __restrict__ B1h, const bf* __restrict__ B1l, long sB1, int ldb1, int K1,
    const bf* __restrict__ A2h, const bf* __restrict__ A2l, long sA2, int lda2,
    const bf* __restrict__ B2h, const bf* __restrict__ B2l, long sB2, int ldb2, int K2,
    void* __restrict__ Chv, void* __restrict__ Clv, long sC, int ldc,
    uint32_t sm, int bm, int bn, long z)
{
    const int tid = threadIdx.x, lane = tid & 31, wid = tid >> 5;
    const int wm = wid & 1, wn = (wid >> 1) & 1;

    float acc[4][8][4];
#pragma unroll
    for (int i = 0; i < 4; i++)
#pragma unroll
        for (int j = 0; j < 8; j++)
#pragma unroll
            for (int q = 0; q < 4; q++) acc[i][j][q] = 0.0f;

    {
        long ao = z * sA1 + (TA1 == 0 ? (long)bm * lda1 : (long)bm);
        long bo = z * sB1 + (TB1 == 0 ? (long)bn * ldb1 : (long)bn);
        run_k<TA1, TB1>(acc, sm, A1h + ao, A1l + ao, lda1,
                        B1h + bo, B1l + bo, ldb1, K1, true, tid, lane, wm, wn);
    }
    if (K2 > 0) {
        long ao = z * sA2 + (TA2 == 0 ? (long)bm * lda2 : (long)bm);
        long bo = z * sB2 + (TB2 == 0 ? (long)bn * ldb2 : (long)bn);
        run_k<TA2, TB2>(acc, sm, A2h + ao, A2l + ao, lda2,
                        B2h + bo, B2l + bo, ldb2, K2, false, tid, lane, wm, wn);
    }

    // epilogue
    const long rbase = z * sC;
#pragma unroll
    for (int mf = 0; mf < 4; mf++) {
#pragma unroll
        for (int nf = 0; nf < 8; nf++) {
            float* d = acc[mf][nf];
            int r = bm + wm * 64 + mf * 16 + (lane >> 2);
            int c = bn + wn * 64 + nf * 8 + (lane & 3) * 2;
            long i0 = rbase + (long)r * ldc + c;
            long i1 = i0 + 8L * ldc;
            if (MODE == 0) {
                float* C = (float*)Chv;
                *(float2*)(C + i0) = make_float2(d[0], d[1]);
                *(float2*)(C + i1) = make_float2(d[2], d[3]);
            } else {
                float v0 = d[0], v1 = d[1], v2 = d[2], v3 = d[3];
                if (MODE == 2) {
                    if (c     > r)     v0 = 0.0f;
                    if (c + 1 > r)     v1 = 0.0f;
                    if (c     > r + 8) v2 = 0.0f;
                    if (c + 1 > r + 8) v3 = 0.0f;
                }
                uint32_t hi0, lo0, hi1, lo1;
                split2(v0, v1, hi0, lo0);
                split2(v2, v3, hi1, lo1);
                bf* Ch = (bf*)Chv; bf* Cl = (bf*)Clv;
                *(uint32_t*)(Ch + i0) = hi0;
                *(uint32_t*)(Cl + i0) = lo0;
                *(uint32_t*)(Ch + i1) = hi1;
                *(uint32_t*)(Cl + i1) = lo1;
            }
        }
    }
}

template <int MODE, int TA1, int TB1, int TA2, int TB2>
__global__ __launch_bounds__(NTHR, 2)
void gemm2(const bf* __restrict__ A1h, const bf* __restrict__ A1l, long sA1, int lda1,
           const bf* __restrict__ B1h, const bf* __restrict__ B1l, long sB1, int ldb1, int K1,
           const bf* __restrict__ A2h, const bf* __restrict__ A2l, long sA2, int lda2,
           const bf* __restrict__ B2h, const bf* __restrict__ B2l, long sB2, int ldb2, int K2,
           void* __restrict__ Chv, void* __restrict__ Clv, long sC, int ldc)
{
    extern __shared__ __align__(128) char dsm[];
    gemm_core<MODE, TA1, TB1, TA2, TB2>(
        A1h, A1l, sA1, lda1, B1h, B1l, sB1, ldb1, K1,
        A2h, A2l, sA2, lda2, B2h, B2l, sB2, ldb2, K2,
        Chv, Clv, sC, ldc,
        smem_u32(dsm), blockIdx.y * 128, blockIdx.x * 128, blockIdx.z);
}

// ---------------------------------------------------------------------------
// scores kernel: masked intra-chunk q.k^T, with fully-masked-tile skip
// ---------------------------------------------------------------------------
__global__ __launch_bounds__(NTHR, 2)
void scores_kern(const bf* __restrict__ qkvh, const bf* __restrict__ qkvl,
                 bf* __restrict__ sch, bf* __restrict__ scl)
{
    extern __shared__ __align__(128) char dsm[];
    const int id = blockIdx.x;
    const int tid = threadIdx.x;
    const int x = id & 1, y = (id >> 1) & 1;
    const long z = id >> 2;
    const int bm = y * 128, bn = x * 128;
    if (bn > bm) {
        bf* Ch = sch + z * SSQ;
        bf* Cl = scl + z * SSQ;
        const uint4 zz = make_uint4(0u, 0u, 0u, 0u);
        for (int i = tid; i < 2048; i += NTHR) {
            int r = i >> 4, q = i & 15;
            long off = (long)r * CCHUNK + 128 + q * 8;
            *(uint4*)(Ch + off) = zz;
            *(uint4*)(Cl + off) = zz;
        }
        return;
    }
    gemm_core<2, 0, 0, 0, 0>(qkvh, qkvl, CHQ, 3 * DIMD,
                             qkvh + DIMD, qkvl + DIMD, CHQ, 3 * DIMD, DIMD,
                             nullptr, nullptr, 0, 0, nullptr, nullptr, 0, 0, 0,
                             sch, scl, SSQ, CCHUNK,
                             smem_u32(dsm), bm, bn, z);
}

// ---------------------------------------------------------------------------
// fused prep: weight transpose+split (ids 0..1023) + x pack (ids 1024..5119)
// ---------------------------------------------------------------------------
__global__ __launch_bounds__(256)
void prep(const float4* __restrict__ x4, bf* __restrict__ xh, bf* __restrict__ xl, int n4,
          const float* __restrict__ w0, const float* __restrict__ w1,
          const float* __restrict__ w2, const float* __restrict__ w3,
          bf* __restrict__ th, bf* __restrict__ tl)
{
    const int id = blockIdx.x;
    if (id < 1024) {
        const float* Ws[4] = {w0, w1, w2, w3};
        const int wx = id & 15, wy = (id >> 4) & 15, wz = id >> 8;
        const float* W = Ws[wz];
        __shared__ float s[32][33];
        int n0 = wx * 32, k0 = wy * 32;
        int tx = threadIdx.x & 31, ty = threadIdx.x >> 5;
#pragma unroll
        for (int i = 0; i < 4; i++)
            s[ty + 8 * i][tx] = W[(long)(k0 + ty + 8 * i) * DIMD + n0 + tx];
        __syncthreads();
#pragma unroll
        for (int i = 0; i < 4; i++) {
            float v = s[tx][ty + 8 * i];
            uint16_t h, l;
            split1(v, h, l);
            size_t o = (size_t)wz * DIMD * DIMD + (size_t)(n0 + ty + 8 * i) * DIMD + k0 + tx;
            ((uint16_t*)th)[o] = h;
            ((uint16_t*)tl)[o] = l;
        }
    } else {
        const int idp = id - 1024;
        for (int i = idp * 256 + threadIdx.x; i < n4; i += 4096 * 256) {
            float4 f = x4[i];
            uint32_t h0, l0, h1, l1;
            split2(f.x, f.y, h0, l0);
            split2(f.z, f.w, h1, l1);
            *(uint2*)(xh + (size_t)i * 4) = make_uint2(h0, h1);
            *(uint2*)(xl + (size_t)i * 4) = make_uint2(l0, l1);
        }
    }
}

__global__ __launch_bounds__(256)
void prefix_split(const float* __restrict__ st, bf* __restrict__ ph, bf* __restrict__ pl)
{
    const int e = blockIdx.x * 256 + threadIdx.x;
    const int b = blockIdx.y;
    float run = 0.0f;
    for (int c = 0; c < CHUNKS_PER_BATCH; c++) {
        size_t idx = ((size_t)(b * CHUNKS_PER_BATCH + c)) * ((size_t)DIMD * DIMD) + e;
        uint16_t h, l;
        split1(run, h, l);
        ((uint16_t*)ph)[idx] = h;
        ((uint16_t*)pl)[idx] = l;
        run += st[idx];
    }
}

// ---------------------------------------------------------------------------
// launcher
// ---------------------------------------------------------------------------
extern "C" void kernel_launch(void* const* d_in, const int* in_sizes, int n_in,
                              void* d_out, int out_size)
{
    int xi = 0;
    for (int i = 0; i < n_in; i++)
        if (in_sizes[i] == (int)(ROWS_TOTAL * DIMD)) { xi = i; break; }
    const float* W[4]; int wi = 0;
    for (int i = 0; i < n_in && wi < 4; i++) { if (i == xi) continue; W[wi++] = (const float*)d_in[i]; }
    const float* x = (const float*)d_in[xi];

    bf *xh, *xl, *qkvh, *qkvl, *yh, *yl, *wth, *wtl, *ph, *pl, *sch, *scl;
    float *st;
    cudaGetSymbolAddress((void**)&xh, g_xh);     cudaGetSymbolAddress((void**)&xl, g_xl);
    cudaGetSymbolAddress((void**)&qkvh, g_qkvh); cudaGetSymbolAddress((void**)&qkvl, g_qkvl);
    cudaGetSymbolAddress((void**)&yh, g_yh);     cudaGetSymbolAddress((void**)&yl, g_yl);
    cudaGetSymbolAddress((void**)&wth, g_wth);   cudaGetSymbolAddress((void**)&wtl, g_wtl);
    cudaGetSymbolAddress((void**)&ph, g_ph);     cudaGetSymbolAddress((void**)&pl, g_pl);
    cudaGetSymbolAddress((void**)&sch, g_sch);   cudaGetSymbolAddress((void**)&scl, g_scl);
    cudaGetSymbolAddress((void**)&st, g_st);

    cudaFuncSetAttribute(gemm2<1,0,0,0,0>, cudaFuncAttributeMaxDynamicSharedMemorySize, GSMEM);
    cudaFuncSetAttribute(gemm2<0,1,1,0,0>, cudaFuncAttributeMaxDynamicSharedMemorySize, GSMEM);
    cudaFuncSetAttribute(gemm2<1,0,0,0,1>, cudaFuncAttributeMaxDynamicSharedMemorySize, GSMEM);
    cudaFuncSetAttribute(gemm2<0,0,0,0,0>, cudaFuncAttributeMaxDynamicSharedMemorySize, GSMEM);
    cudaFuncSetAttribute(scores_kern, cudaFuncAttributeMaxDynamicSharedMemorySize, GSMEM);

    // prep: pack x + transpose/split weights (one launch)
    prep<<<5120, 256>>>((const float4*)x, xh, xl, (int)(NE / 4),
                        W[0], W[1], W[2], W[3], wth, wtl);

    // fused q|k|v projection: [16384,1536] = x @ [Wq|Wk|Wv]
    gemm2<1,0,0,0,0><<<dim3(12, 128, 1), NTHR, GSMEM>>>(
        xh, xl, 0, DIMD, wth, wtl, 0, DIMD, DIMD,
        nullptr, nullptr, 0, 0, nullptr, nullptr, 0, 0, 0,
        qkvh, qkvl, 0, 3 * DIMD);

    // intra-chunk masked scores (no transposes needed anymore)
    scores_kern<<<256, NTHR, GSMEM>>>(qkvh, qkvl, sch, scl);

    // per-chunk state S_c[dv][dk] = sum_t V[t][dv] K[t][dk]  (f32)
    // A = v (token-major, trans), B = k (token-major, trans), K = 256 t
    gemm2<0,1,1,0,0><<<dim3(4, 4, NCHUNKS), NTHR, GSMEM>>>(
        qkvh + 2 * DIMD, qkvl + 2 * DIMD, CHQ, 3 * DIMD,
        qkvh + DIMD,     qkvl + DIMD,     CHQ, 3 * DIMD, CCHUNK,
        nullptr, nullptr, 0, 0, nullptr, nullptr, 0, 0, 0,
        st, nullptr, STQ, DIMD);

    // exclusive prefix over chunks -> P planes
    prefix_split<<<dim3((unsigned)(STQ / 256), 4), 256>>>(st, ph, pl);

    // fused Y_c = Q_c @ P_c^T + scores_c @ V_c  -> split planes
    // run2: A = scores (normal), B = v (token-major, trans)
    gemm2<1,0,0,0,1><<<dim3(4, 2, NCHUNKS), NTHR, GSMEM>>>(
        qkvh, qkvl, CHQ, 3 * DIMD, ph, pl, STQ, DIMD, DIMD,
        sch, scl, SSQ, CCHUNK,
        qkvh + 2 * DIMD, qkvl + 2 * DIMD, CHQ, 3 * DIMD, CCHUNK,
        yh, yl, CHY, DIMD);

    // out = Y @ Wo (f32)
    gemm2<0,0,0,0,0><<<dim3(4, 128, 1), NTHR, GSMEM>>>(
        yh, yl, 0, DIMD, wth + 3 * STQ, wtl + 3 * STQ, 0, DIMD, DIMD,
        nullptr, nullptr, 0, 0, nullptr, nullptr, 0, 0, 0,
        d_out, nullptr, 0, DIMD);
}

// round 15
// speedup vs baseline: 1.1525x; 1.0025x over previous
#include <cuda_runtime.h>
#include <cuda_bf16.h>
#include <cstdint>
#include <cstddef>

// Problem constants: B=4, S=4096, D=512
#define ROWS_TOTAL 16384
#define DIMD 512
#define CCHUNK 256
#define NCHUNKS 64
#define CHUNKS_PER_BATCH 16

#define NE  ((size_t)ROWS_TOTAL * DIMD)             // 8,388,608
#define NQKV ((size_t)ROWS_TOTAL * 3 * DIMD)        // 25,165,824
#define STN ((size_t)NCHUNKS * DIMD * DIMD)         // 16,777,216
#define SCN ((size_t)NCHUNKS * CCHUNK * CCHUNK)     // 4,194,304

#define SSQ ((long)CCHUNK * CCHUNK)                 // 65536
#define CHQ ((long)CCHUNK * 3 * DIMD)               // 393216
#define CHY ((long)CCHUNK * DIMD)                   // 131072
#define STQ ((long)DIMD * DIMD)                     // 262144

typedef __nv_bfloat16 bf;

// ---------------------------------------------------------------------------
// Scratch (static device globals)
// ---------------------------------------------------------------------------
__device__ __align__(16) bf g_xh[NE], g_xl[NE];
__device__ __align__(16) bf g_qkvh[NQKV], g_qkvl[NQKV];     // [16384][1536]
__device__ __align__(16) bf g_yh[NE], g_yl[NE];
__device__ __align__(16) bf g_wth[(size_t)4 * DIMD * DIMD]; // [4][512 n][512 k] = W^T
__device__ __align__(16) bf g_wtl[(size_t)4 * DIMD * DIMD];
__device__ __align__(16) bf g_ph[STN], g_pl[STN];
__device__ __align__(16) bf g_sch[SCN], g_scl[SCN];
__device__ __align__(16) float g_st[STN];

// ---------------------------------------------------------------------------
// helpers
// ---------------------------------------------------------------------------
__device__ __forceinline__ uint32_t smem_u32(const void* p) {
    uint32_t a;
    asm("{ .reg .u64 t; cvta.to.shared.u64 t, %1; cvt.u32.u64 %0, t; }" : "=r"(a) : "l"(p));
    return a;
}
__device__ __forceinline__ void cp16(uint32_t dst, const void* src) {
    asm volatile("cp.async.cg.shared.global [%0], [%1], 16;" :: "r"(dst), "l"(src));
}
#define CP_COMMIT() asm volatile("cp.async.commit_group;" ::: "memory")
template <int N> __device__ __forceinline__ void cp_wait() {
    asm volatile("cp.async.wait_group %0;" :: "n"(N) : "memory");
}
__device__ __forceinline__ void ldm4(uint32_t* r, uint32_t addr) {
    asm volatile("ldmatrix.sync.aligned.m8n8.x4.shared.b16 {%0,%1,%2,%3}, [%4];"
                 : "=r"(r[0]), "=r"(r[1]), "=r"(r[2]), "=r"(r[3]) : "r"(addr));
}
__device__ __forceinline__ void ldm4t(uint32_t* r, uint32_t addr) {
    asm volatile("ldmatrix.sync.aligned.m8n8.x4.trans.shared.b16 {%0,%1,%2,%3}, [%4];"
                 : "=r"(r[0]), "=r"(r[1]), "=r"(r[2]), "=r"(r[3]) : "r"(addr));
}
__device__ __forceinline__ void mma16816(float* d, const uint32_t* a, uint32_t b0, uint32_t b1) {
    asm volatile("mma.sync.aligned.m16n8k16.row.col.f32.bf16.bf16.f32 "
                 "{%0,%1,%2,%3},{%4,%5,%6,%7},{%8,%9},{%0,%1,%2,%3};"
                 : "+f"(d[0]), "+f"(d[1]), "+f"(d[2]), "+f"(d[3])
                 : "r"(a[0]), "r"(a[1]), "r"(a[2]), "r"(a[3]), "r"(b0), "r"(b1));
}
__device__ __forceinline__ void split1(float v, uint16_t& h, uint16_t& l) {
    __nv_bfloat16 hb = __float2bfloat16(v);
    __nv_bfloat16 lb = __float2bfloat16(v - __bfloat162float(hb));
    h = __bfloat16_as_ushort(hb);
    l = __bfloat16_as_ushort(lb);
}
__device__ __forceinline__ void split2(float v0, float v1, uint32_t& hi, uint32_t& lo) {
    uint16_t h0, l0, h1, l1;
    split1(v0, h0, l0); split1(v1, h1, l1);
    hi = (uint32_t)h0 | ((uint32_t)h1 << 16);
    lo = (uint32_t)l0 | ((uint32_t)l1 << 16);
}

// ---------------------------------------------------------------------------
// GEMM core: CTA 128x128, 4 warps (2m x 2n), warp tile 64x64, 3-stage pipeline.
// Operand types: T=0 normal (stored [m][k]); T=1 trans (stored [k][m], ldm4t).
// ---------------------------------------------------------------------------
#define NTHR 128
#define STAGE_BYTES 32768
#define GSMEM (3 * STAGE_BYTES)   // 96 KB -> 2 CTAs/SM

template <int TA, int TB>
__device__ __forceinline__ void run_k(
    float (&acc)[4][8][4], uint32_t sm,
    const bf* __restrict__ Ah, const bf* __restrict__ Al, int lda,
    const bf* __restrict__ Bh, const bf* __restrict__ Bl, int ldb,
    int K, bool first, int tid, int lane, int wm, int wn)
{
    auto load = [&](int c, int buf) {
        const int k0 = c * 32;
        const uint32_t sb = sm + buf * STAGE_BYTES;
#pragma unroll
        for (int i = 0; i < 8; i++) {
            int e = tid + NTHR * i;             // A: 1024 cp16
            if (TA == 0) {
                int row = e >> 3, ch = e & 7;
                const bf* src = (ch < 4 ? Ah : Al) + (long)row * lda + k0 + (ch & 3) * 8;
                cp16(sb + (uint32_t)(row * 128 + ((ch ^ (row & 7)) << 4)), src);
            } else {
                int p = e >> 9, t = (e >> 4) & 31, mg = e & 15;
                const bf* src = (p ? Al : Ah) + (long)(k0 + t) * lda + mg * 8;
                cp16(sb + (uint32_t)(p * 8192 + t * 256 + ((mg >> 3) & 1) * 128 +
                                     (((mg & 7) ^ (t & 7)) << 4)), src);
            }
        }
#pragma unroll
        for (int i = 0; i < 8; i++) {
            int e = tid + NTHR * i;             // B: 1024 cp16
            if (TB == 0) {
                int row = e >> 3, ch = e & 7;
                const bf* src = (ch < 4 ? Bh : Bl) + (long)row * ldb + k0 + (ch & 3) * 8;
                cp16(sb + 16384 + (uint32_t)(row * 128 + ((ch ^ (row & 7)) << 4)), src);
            } else {
                int p = e >> 9, t = (e >> 4) & 31, mg = e & 15;
                const bf* src = (p ? Bl : Bh) + (long)(k0 + t) * ldb + mg * 8;
                cp16(sb + 16384 + (uint32_t)(p * 8192 + t * 256 + ((mg >> 3) & 1) * 128 +
                                             (((mg & 7) ^ (t & 7)) << 4)), src);
            }
        }
    };

    auto compute = [&](int buf) {
        const uint32_t ba = sm + buf * STAGE_BYTES;
        const uint32_t bb = ba + 16384;
#pragma unroll
        for (int kh2 = 0; kh2 < 2; kh2++) {
            uint32_t ahf[4][4], alf[4][4], bhf[4][4], blf[4][4];
            // ---- A fragments ----
            if (TA == 0) {
                int arow = wm * 64 + (lane & 7) + ((lane >> 3) & 1) * 8;
                int ach = kh2 * 2 + (lane >> 4);
#pragma unroll
                for (int mf = 0; mf < 4; mf++) {
                    int row = arow + mf * 16;
                    ldm4(ahf[mf], ba + row * 128 + ((ach ^ (row & 7)) << 4));
                }
#pragma unroll
                for (int mf = 0; mf < 4; mf++) {
                    int row = arow + mf * 16;
                    ldm4(alf[mf], ba + row * 128 + (((ach + 4) ^ (row & 7)) << 4));
                }
            } else {
                int t = kh2 * 16 + ((lane >> 4) & 1) * 8 + (lane & 7);
                int mh = (lane >> 3) & 1;
#pragma unroll
                for (int mf = 0; mf < 4; mf++) {
                    int mg = wm * 8 + mf * 2 + mh;
                    uint32_t off = (uint32_t)(t * 256 + ((mg >> 3) & 1) * 128 +
                                              (((mg & 7) ^ (t & 7)) << 4));
                    ldm4t(ahf[mf], ba + off);
                }
#pragma unroll
                for (int mf = 0; mf < 4; mf++) {
                    int mg = wm * 8 + mf * 2 + mh;
                    uint32_t off = (uint32_t)(t * 256 + ((mg >> 3) & 1) * 128 +
                                              (((mg & 7) ^ (t & 7)) << 4));
                    ldm4t(alf[mf], ba + 8192 + off);
                }
            }
            // ---- B fragments ----
            if (TB == 0) {
                int brow = wn * 64 + (lane & 7) + (lane >> 4) * 8;
                int bch = kh2 * 2 + ((lane >> 3) & 1);
#pragma unroll
                for (int bi = 0; bi < 4; bi++) {
                    int row = brow + bi * 16;
                    ldm4(bhf[bi], bb + row * 128 + ((bch ^ (row & 7)) << 4));
                }
#pragma unroll
                for (int bi = 0; bi < 4; bi++) {
                    int row = brow + bi * 16;
                    ldm4(blf[bi], bb + row * 128 + (((bch + 4) ^ (row & 7)) << 4));
                }
            } else {
                int t = kh2 * 16 + ((lane >> 3) & 1) * 8 + (lane & 7);
                int nh = (lane >> 4) & 1;
#pragma unroll
                for (int bi = 0; bi < 4; bi++) {
                    int ng = wn * 8 + bi * 2 + nh;
                    uint32_t off = (uint32_t)(t * 256 + ((ng >> 3) & 1) * 128 +
                                              (((ng & 7) ^ (t & 7)) << 4));
                    ldm4t(bhf[bi], bb + off);
                }
#pragma unroll
                for (int bi = 0; bi < 4; bi++) {
                    int ng = wn * 8 + bi * 2 + nh;
                    uint32_t off = (uint32_t)(t * 256 + ((ng >> 3) & 1) * 128 +
                                              (((ng & 7) ^ (t & 7)) << 4));
                    ldm4t(blf[bi], bb + 8192 + off);
                }
            }
            // ---- 96 MMAs, term-major; per-acc order hh, hl, lh ----
#pragma unroll
            for (int mf = 0; mf < 4; mf++)
#pragma unroll
                for (int nf = 0; nf < 8; nf++)
                    mma16816(acc[mf][nf], ahf[mf], bhf[nf >> 1][2 * (nf & 1)], bhf[nf >> 1][2 * (nf & 1) + 1]);
#pragma unroll
            for (int mf = 0; mf < 4; mf++)
#pragma unroll
                for (int nf = 0; nf < 8; nf++)
                    mma16816(acc[mf][nf], ahf[mf], blf[nf >> 1][2 * (nf & 1)], blf[nf >> 1][2 * (nf & 1) + 1]);
#pragma unroll
            for (int mf = 0; mf < 4; mf++)
#pragma unroll
                for (int nf = 0; nf < 8; nf++)
                    mma16816(acc[mf][nf], alf[mf], bhf[nf >> 1][2 * (nf & 1)], bhf[nf >> 1][2 * (nf & 1) + 1]);
        }
    };

    const int nch = K >> 5;
    if (!first) __syncthreads();
    load(0, 0); CP_COMMIT();
    if (nch > 1) { load(1, 1); CP_COMMIT(); }
    for (int c = 0; c < nch; c++) {
        if (c + 1 < nch) cp_wait<1>(); else cp_wait<0>();
        __syncthreads();
        if (c + 2 < nch) { load(c + 2, (c + 2) % 3); CP_COMMIT(); }
        compute(c % 3);
    }
}

// gemm_core: K1 may be 0 at runtime (run1 skipped; identical result since the
// skipped contributions are exact +0 accumulations).
template <int MODE, int TA1, int TB1, int TA2, int TB2>
__device__ __forceinline__ void gemm_core(
    const bf* __restrict__ A1h, const bf* __restrict__ A1l, long sA1, int lda1,
    const bf* __restrict__ B1h, const bf* __restrict__ B1l, long sB1, int ldb1, int K1,
    const bf* __restrict__ A2h, const bf* __restrict__ A2l, long sA2, int lda2,
    const bf* __restrict__ B2h, const bf* __restrict__ B2l, long sB2, int ldb2, int K2,
    void* __restrict__ Chv, void* __restrict__ Clv, long sC, int ldc,
    uint32_t sm, int bm, int bn, long z)
{
    const int tid = threadIdx.x, lane = tid & 31, wid = tid >> 5;
    const int wm = wid & 1, wn = (wid >> 1) & 1;

    float acc[4][8][4];
#pragma unroll
    for (int i = 0; i < 4; i++)
#pragma unroll
        for (int j = 0; j < 8; j++)
#pragma unroll
            for (int q = 0; q < 4; q++) acc[i][j][q] = 0.0f;

    if (K1 > 0) {
        long ao = z * sA1 + (TA1 == 0 ? (long)bm * lda1 : (long)bm);
        long bo = z * sB1 + (TB1 == 0 ? (long)bn * ldb1 : (long)bn);
        run_k<TA1, TB1>(acc, sm, A1h + ao, A1l + ao, lda1,
                        B1h + bo, B1l + bo, ldb1, K1, true, tid, lane, wm, wn);
    }
    if (K2 > 0) {
        long ao = z * sA2 + (TA2 == 0 ? (long)bm * lda2 : (long)bm);
        long bo = z * sB2 + (TB2 == 0 ? (long)bn * ldb2 : (long)bn);
        run_k<TA2, TB2>(acc, sm, A2h + ao, A2l + ao, lda2,
                        B2h + bo, B2l + bo, ldb2, K2, (K1 <= 0), tid, lane, wm, wn);
    }

    // epilogue
    const long rbase = z * sC;
#pragma unroll
    for (int mf = 0; mf < 4; mf++) {
#pragma unroll
        for (int nf = 0; nf < 8; nf++) {
            float* d = acc[mf][nf];
            int r = bm + wm * 64 + mf * 16 + (lane >> 2);
            int c = bn + wn * 64 + nf * 8 + (lane & 3) * 2;
            long i0 = rbase + (long)r * ldc + c;
            long i1 = i0 + 8L * ldc;
            if (MODE == 0) {
                float* C = (float*)Chv;
                *(float2*)(C + i0) = make_float2(d[0], d[1]);
                *(float2*)(C + i1) = make_float2(d[2], d[3]);
            } else {
                float v0 = d[0], v1 = d[1], v2 = d[2], v3 = d[3];
                if (MODE == 2) {
                    if (c     > r)     v0 = 0.0f;
                    if (c + 1 > r)     v1 = 0.0f;
                    if (c     > r + 8) v2 = 0.0f;
                    if (c + 1 > r + 8) v3 = 0.0f;
                }
                uint32_t hi0, lo0, hi1, lo1;
                split2(v0, v1, hi0, lo0);
                split2(v2, v3, hi1, lo1);
                bf* Ch = (bf*)Chv; bf* Cl = (bf*)Clv;
                *(uint32_t*)(Ch + i0) = hi0;
                *(uint32_t*)(Cl + i0) = lo0;
                *(uint32_t*)(Ch + i1) = hi1;
                *(uint32_t*)(Cl + i1) = lo1;
            }
        }
    }
}

template <int MODE, int TA1, int TB1, int TA2, int TB2>
__global__ __launch_bounds__(NTHR, 2)
void gemm2(const bf* __restrict__ A1h, const bf* __restrict__ A1l, long sA1, int lda1,
           const bf* __restrict__ B1h, const bf* __restrict__ B1l, long sB1, int ldb1, int K1,
           const bf* __restrict__ A2h, const bf* __restrict__ A2l, long sA2, int lda2,
           const bf* __restrict__ B2h, const bf* __restrict__ B2l, long sB2, int ldb2, int K2,
           void* __restrict__ Chv, void* __restrict__ Clv, long sC, int ldc)
{
    extern __shared__ __align__(128) char dsm[];
    gemm_core<MODE, TA1, TB1, TA2, TB2>(
        A1h, A1l, sA1, lda1, B1h, B1l, sB1, ldb1, K1,
        A2h, A2l, sA2, lda2, B2h, B2l, sB2, ldb2, K2,
        Chv, Clv, sC, ldc,
        smem_u32(dsm), blockIdx.y * 128, blockIdx.x * 128, blockIdx.z);
}

// ---------------------------------------------------------------------------
// fused state GEMM (ids 0..1023) + lower-tri scores tiles (ids 1024..1215)
// ---------------------------------------------------------------------------
__global__ __launch_bounds__(NTHR, 2)
void state_scores(const bf* __restrict__ qkvh, const bf* __restrict__ qkvl,
                  float* __restrict__ st,
                  bf* __restrict__ sch, bf* __restrict__ scl)
{
    extern __shared__ __align__(128) char dsm[];
    const int id = blockIdx.x;
    if (id < 1024) {
        // state: S_c[dv][dk] = sum_t V[t][dv] K[t][dk]
        const int x = id & 3, y = (id >> 2) & 3;
        const long z = id >> 4;
        gemm_core<0, 1, 1, 0, 0>(
            qkvh + 2 * DIMD, qkvl + 2 * DIMD, CHQ, 3 * DIMD,
            qkvh + DIMD,     qkvl + DIMD,     CHQ, 3 * DIMD, CCHUNK,
            nullptr, nullptr, 0, 0, nullptr, nullptr, 0, 0, 0,
            st, nullptr, STQ, DIMD,
            smem_u32(dsm), y * 128, x * 128, z);
    } else {
        // scores lower-tri tiles: tile 0=(0,0), 1=(1,0), 2=(1,1)
        const int t = id - 1024;
        const long z = t / 3;
        const int tile = t - (int)z * 3;
        const int bm = (tile == 0) ? 0 : 128;
        const int bn = (tile == 2) ? 128 : 0;
        gemm_core<2, 0, 0, 0, 0>(
            qkvh, qkvl, CHQ, 3 * DIMD,
            qkvh + DIMD, qkvl + DIMD, CHQ, 3 * DIMD, DIMD,
            nullptr, nullptr, 0, 0, nullptr, nullptr, 0, 0, 0,
            sch, scl, SSQ, CCHUNK,
            smem_u32(dsm), bm, bn, z);
    }
}

// ---------------------------------------------------------------------------
// Y kernel: Y_c = Q_c @ P_c^T + scores_c @ V_c  (with structural zero skips)
// ---------------------------------------------------------------------------
__global__ __launch_bounds__(NTHR, 2)
void y_kern(const bf* __restrict__ qkvh, const bf* __restrict__ qkvl,
            const bf* __restrict__ ph, const bf* __restrict__ pl,
            const bf* __restrict__ sch, const bf* __restrict__ scl,
            bf* __restrict__ yh, bf* __restrict__ yl)
{
    extern __shared__ __align__(128) char dsm[];
    const long z = blockIdx.z;
    const int bm = blockIdx.y * 128, bn = blockIdx.x * 128;
    const int K1 = ((z % CHUNKS_PER_BATCH) == 0) ? 0 : DIMD;   // P_0 = 0
    const int K2 = (blockIdx.y == 0) ? 128 : CCHUNK;           // scores cols >127 zero for rows <128
    gemm_core<1, 0, 0, 0, 1>(
        qkvh, qkvl, CHQ, 3 * DIMD, ph, pl, STQ, DIMD, K1,
        sch, scl, SSQ, CCHUNK,
        qkvh + 2 * DIMD, qkvl + 2 * DIMD, CHQ, 3 * DIMD, K2,
        yh, yl, CHY, DIMD,
        smem_u32(dsm), bm, bn, z);
}

// ---------------------------------------------------------------------------
// fused prep: weight transpose+split (ids 0..1023) + x pack (ids 1024..5119)
// ---------------------------------------------------------------------------
__global__ __launch_bounds__(256)
void prep(const float4* __restrict__ x4, bf* __restrict__ xh, bf* __restrict__ xl, int n4,
          const float* __restrict__ w0, const float* __restrict__ w1,
          const float* __restrict__ w2, const float* __restrict__ w3,
          bf* __restrict__ th, bf* __restrict__ tl)
{
    const int id = blockIdx.x;
    if (id < 1024) {
        const float* Ws[4] = {w0, w1, w2, w3};
        const int wx = id & 15, wy = (id >> 4) & 15, wz = id >> 8;
        const float* W = Ws[wz];
        __shared__ float s[32][33];
        int n0 = wx * 32, k0 = wy * 32;
        int tx = threadIdx.x & 31, ty = threadIdx.x >> 5;
#pragma unroll
        for (int i = 0; i < 4; i++)
            s[ty + 8 * i][tx] = W[(long)(k0 + ty + 8 * i) * DIMD + n0 + tx];
        __syncthreads();
#pragma unroll
        for (int i = 0; i < 4; i++) {
            float v = s[tx][ty + 8 * i];
            uint16_t h, l;
            split1(v, h, l);
            size_t o = (size_t)wz * DIMD * DIMD + (size_t)(n0 + ty + 8 * i) * DIMD + k0 + tx;
            ((uint16_t*)th)[o] = h;
            ((uint16_t*)tl)[o] = l;
        }
    } else {
        const int idp = id - 1024;
        for (int i = idp * 256 + threadIdx.x; i < n4; i += 4096 * 256) {
            float4 f = x4[i];
            uint32_t h0, l0, h1, l1;
            split2(f.x, f.y, h0, l0);
            split2(f.z, f.w, h1, l1);
            *(uint2*)(xh + (size_t)i * 4) = make_uint2(h0, h1);
            *(uint2*)(xl + (size_t)i * 4) = make_uint2(l0, l1);
        }
    }
}

__global__ __launch_bounds__(256)
void prefix_split(const float* __restrict__ st, bf* __restrict__ ph, bf* __restrict__ pl)
{
    const int e = blockIdx.x * 256 + threadIdx.x;
    const int b = blockIdx.y;
    float run = 0.0f;
    for (int c = 0; c < CHUNKS_PER_BATCH; c++) {
        size_t idx = ((size_t)(b * CHUNKS_PER_BATCH + c)) * ((size_t)DIMD * DIMD) + e;
        uint16_t h, l;
        split1(run, h, l);
        ((uint16_t*)ph)[idx] = h;
        ((uint16_t*)pl)[idx] = l;
        run += st[idx];
    }
}

// ---------------------------------------------------------------------------
// launcher
// ---------------------------------------------------------------------------
extern "C" void kernel_launch(void* const* d_in, const int* in_sizes, int n_in,
                              void* d_out, int out_size)
{
    int xi = 0;
    for (int i = 0; i < n_in; i++)
        if (in_sizes[i] == (int)(ROWS_TOTAL * DIMD)) { xi = i; break; }
    const float* W[4]; int wi = 0;
    for (int i = 0; i < n_in && wi < 4; i++) { if (i == xi) continue; W[wi++] = (const float*)d_in[i]; }
    const float* x = (const float*)d_in[xi];

    bf *xh, *xl, *qkvh, *qkvl, *yh, *yl, *wth, *wtl, *ph, *pl, *sch, *scl;
    float *st;
    cudaGetSymbolAddress((void**)&xh, g_xh);     cudaGetSymbolAddress((void**)&xl, g_xl);
    cudaGetSymbolAddress((void**)&qkvh, g_qkvh); cudaGetSymbolAddress((void**)&qkvl, g_qkvl);
    cudaGetSymbolAddress((void**)&yh, g_yh);     cudaGetSymbolAddress((void**)&yl, g_yl);
    cudaGetSymbolAddress((void**)&wth, g_wth);   cudaGetSymbolAddress((void**)&wtl, g_wtl);
    cudaGetSymbolAddress((void**)&ph, g_ph);     cudaGetSymbolAddress((void**)&pl, g_pl);
    cudaGetSymbolAddress((void**)&sch, g_sch);   cudaGetSymbolAddress((void**)&scl, g_scl);
    cudaGetSymbolAddress((void**)&st, g_st);

    cudaFuncSetAttribute(gemm2<1,0,0,0,0>, cudaFuncAttributeMaxDynamicSharedMemorySize, GSMEM);
    cudaFuncSetAttribute(gemm2<0,0,0,0,0>, cudaFuncAttributeMaxDynamicSharedMemorySize, GSMEM);
    cudaFuncSetAttribute(state_scores, cudaFuncAttributeMaxDynamicSharedMemorySize, GSMEM);
    cudaFuncSetAttribute(y_kern, cudaFuncAttributeMaxDynamicSharedMemorySize, GSMEM);

    // prep: pack x + transpose/split weights (one launch)
    prep<<<5120, 256>>>((const float4*)x, xh, xl, (int)(NE / 4),
                        W[0], W[1], W[2], W[3], wth, wtl);

    // fused q|k|v projection: [16384,1536] = x @ [Wq|Wk|Wv]
    gemm2<1,0,0,0,0><<<dim3(12, 128, 1), NTHR, GSMEM>>>(
        xh, xl, 0, DIMD, wth, wtl, 0, DIMD, DIMD,
        nullptr, nullptr, 0, 0, nullptr, nullptr, 0, 0, 0,
        qkvh, qkvl, 0, 3 * DIMD);

    // fused: state GEMM + masked scores (one launch, 1216 CTAs)
    state_scores<<<1024 + 3 * NCHUNKS, NTHR, GSMEM>>>(qkvh, qkvl, st, sch, scl);

    // exclusive prefix over chunks -> P planes
    prefix_split<<<dim3((unsigned)(STQ / 256), 4), 256>>>(st, ph, pl);

    // Y_c = Q_c @ P_c^T + scores_c @ V_c  (structural zero skips inside)
    y_kern<<<dim3(4, 2, NCHUNKS), NTHR, GSMEM>>>(qkvh, qkvl, ph, pl, sch, scl, yh, yl);

    // out = Y @ Wo (f32)
    gemm2<0,0,0,0,0><<<dim3(4, 128, 1), NTHR, GSMEM>>>(
        yh, yl, 0, DIMD, wth + 3 * STQ, wtl + 3 * STQ, 0, DIMD, DIMD,
        nullptr, nullptr, 0, 0, nullptr, nullptr, 0, 0, 0,
        d_out, nullptr, 0, DIMD);
}

// round 16
// speedup vs baseline: 1.1757x; 1.0201x over previous
#include <cuda_runtime.h>
#include <cuda_bf16.h>
#include <cstdint>
#include <cstddef>

// Problem constants: B=4, S=4096, D=512
#define ROWS_TOTAL 16384
#define DIMD 512
#define CCHUNK 256
#define NCHUNKS 64
#define CHUNKS_PER_BATCH 16

#define NE  ((size_t)ROWS_TOTAL * DIMD)             // 8,388,608
#define NQKV ((size_t)ROWS_TOTAL * 3 * DIMD)        // 25,165,824
#define STN ((size_t)NCHUNKS * DIMD * DIMD)         // 16,777,216
#define SCN ((size_t)NCHUNKS * CCHUNK * CCHUNK)     // 4,194,304

#define SSQ ((long)CCHUNK * CCHUNK)                 // 65536
#define CHQ ((long)CCHUNK * 3 * DIMD)               // 393216
#define CHY ((long)CCHUNK * DIMD)                   // 131072
#define STQ ((long)DIMD * DIMD)                     // 262144

typedef __nv_bfloat16 bf;

// ---------------------------------------------------------------------------
// Scratch (static device globals)
// ---------------------------------------------------------------------------
__device__ __align__(16) bf g_xh[NE], g_xl[NE];
__device__ __align__(16) bf g_qkvh[NQKV], g_qkvl[NQKV];     // [16384][1536]
__device__ __align__(16) bf g_yh[NE], g_yl[NE];
__device__ __align__(16) bf g_wth[(size_t)4 * DIMD * DIMD]; // [4][512 n][512 k] = W^T
__device__ __align__(16) bf g_wtl[(size_t)4 * DIMD * DIMD];
__device__ __align__(16) bf g_ph[STN], g_pl[STN];
__device__ __align__(16) bf g_sch[SCN], g_scl[SCN];
__device__ __align__(16) float g_st[STN];

// ---------------------------------------------------------------------------
// helpers
// ---------------------------------------------------------------------------
__device__ __forceinline__ uint32_t smem_u32(const void* p) {
    uint32_t a;
    asm("{ .reg .u64 t; cvta.to.shared.u64 t, %1; cvt.u32.u64 %0, t; }" : "=r"(a) : "l"(p));
    return a;
}
__device__ __forceinline__ void cp16(uint32_t dst, const void* src) {
    asm volatile("cp.async.cg.shared.global [%0], [%1], 16;" :: "r"(dst), "l"(src));
}
#define CP_COMMIT() asm volatile("cp.async.commit_group;" ::: "memory")
template <int N> __device__ __forceinline__ void cp_wait() {
    asm volatile("cp.async.wait_group %0;" :: "n"(N) : "memory");
}
__device__ __forceinline__ void ldm4(uint32_t* r, uint32_t addr) {
    asm volatile("ldmatrix.sync.aligned.m8n8.x4.shared.b16 {%0,%1,%2,%3}, [%4];"
                 : "=r"(r[0]), "=r"(r[1]), "=r"(r[2]), "=r"(r[3]) : "r"(addr));
}
__device__ __forceinline__ void ldm4t(uint32_t* r, uint32_t addr) {
    asm volatile("ldmatrix.sync.aligned.m8n8.x4.trans.shared.b16 {%0,%1,%2,%3}, [%4];"
                 : "=r"(r[0]), "=r"(r[1]), "=r"(r[2]), "=r"(r[3]) : "r"(addr));
}
__device__ __forceinline__ void mma16816(float* d, const uint32_t* a, uint32_t b0, uint32_t b1) {
    asm volatile("mma.sync.aligned.m16n8k16.row.col.f32.bf16.bf16.f32 "
                 "{%0,%1,%2,%3},{%4,%5,%6,%7},{%8,%9},{%0,%1,%2,%3};"
                 : "+f"(d[0]), "+f"(d[1]), "+f"(d[2]), "+f"(d[3])
                 : "r"(a[0]), "r"(a[1]), "r"(a[2]), "r"(a[3]), "r"(b0), "r"(b1));
}
__device__ __forceinline__ void split1(float v, uint16_t& h, uint16_t& l) {
    __nv_bfloat16 hb = __float2bfloat16(v);
    __nv_bfloat16 lb = __float2bfloat16(v - __bfloat162float(hb));
    h = __bfloat16_as_ushort(hb);
    l = __bfloat16_as_ushort(lb);
}
__device__ __forceinline__ void split2(float v0, float v1, uint32_t& hi, uint32_t& lo) {
    uint16_t h0, l0, h1, l1;
    split1(v0, h0, l0); split1(v1, h1, l1);
    hi = (uint32_t)h0 | ((uint32_t)h1 << 16);
    lo = (uint32_t)l0 | ((uint32_t)l1 << 16);
}

// ---------------------------------------------------------------------------
// GEMM core: CTA 128x128, 4 warps (2m x 2n), warp tile 64x64, 3-stage pipeline.
// Operand types: T=0 normal (stored [m][k]); T=1 trans (stored [k][m], ldm4t).
// act=false: warp participates in loads/syncs but skips LDSM+MMA (acc stays 0;
// used for warp tiles whose every element is masked to zero in the epilogue).
// ---------------------------------------------------------------------------
#define NTHR 128
#define STAGE_BYTES 32768
#define GSMEM (3 * STAGE_BYTES)   // 96 KB -> 2 CTAs/SM

template <int TA, int TB>
__device__ __forceinline__ void run_k(
    float (&acc)[4][8][4], uint32_t sm,
    const bf* __restrict__ Ah, const bf* __restrict__ Al, int lda,
    const bf* __restrict__ Bh, const bf* __restrict__ Bl, int ldb,
    int K, bool first, int tid, int lane, int wm, int wn, bool act)
{
    auto load = [&](int c, int buf) {
        const int k0 = c * 32;
        const uint32_t sb = sm + buf * STAGE_BYTES;
#pragma unroll
        for (int i = 0; i < 8; i++) {
            int e = tid + NTHR * i;             // A: 1024 cp16
            if (TA == 0) {
                int row = e >> 3, ch = e & 7;
                const bf* src = (ch < 4 ? Ah : Al) + (long)row * lda + k0 + (ch & 3) * 8;
                cp16(sb + (uint32_t)(row * 128 + ((ch ^ (row & 7)) << 4)), src);
            } else {
                int p = e >> 9, t = (e >> 4) & 31, mg = e & 15;
                const bf* src = (p ? Al : Ah) + (long)(k0 + t) * lda + mg * 8;
                cp16(sb + (uint32_t)(p * 8192 + t * 256 + ((mg >> 3) & 1) * 128 +
                                     (((mg & 7) ^ (t & 7)) << 4)), src);
            }
        }
#pragma unroll
        for (int i = 0; i < 8; i++) {
            int e = tid + NTHR * i;             // B: 1024 cp16
            if (TB == 0) {
                int row = e >> 3, ch = e & 7;
                const bf* src = (ch < 4 ? Bh : Bl) + (long)row * ldb + k0 + (ch & 3) * 8;
                cp16(sb + 16384 + (uint32_t)(row * 128 + ((ch ^ (row & 7)) << 4)), src);
            } else {
                int p = e >> 9, t = (e >> 4) & 31, mg = e & 15;
                const bf* src = (p ? Bl : Bh) + (long)(k0 + t) * ldb + mg * 8;
                cp16(sb + 16384 + (uint32_t)(p * 8192 + t * 256 + ((mg >> 3) & 1) * 128 +
                                             (((mg & 7) ^ (t & 7)) << 4)), src);
            }
        }
    };

    auto compute = [&](int buf) {
        const uint32_t ba = sm + buf * STAGE_BYTES;
        const uint32_t bb = ba + 16384;
#pragma unroll
        for (int kh2 = 0; kh2 < 2; kh2++) {
            uint32_t ahf[4][4], alf[4][4], bhf[4][4], blf[4][4];
            // ---- A fragments ----
            if (TA == 0) {
                int arow = wm * 64 + (lane & 7) + ((lane >> 3) & 1) * 8;
                int ach = kh2 * 2 + (lane >> 4);
#pragma unroll
                for (int mf = 0; mf < 4; mf++) {
                    int row = arow + mf * 16;
                    ldm4(ahf[mf], ba + row * 128 + ((ach ^ (row & 7)) << 4));
                }
#pragma unroll
                for (int mf = 0; mf < 4; mf++) {
                    int row = arow + mf * 16;
                    ldm4(alf[mf], ba + row * 128 + (((ach + 4) ^ (row & 7)) << 4));
                }
            } else {
                int t = kh2 * 16 + ((lane >> 4) & 1) * 8 + (lane & 7);
                int mh = (lane >> 3) & 1;
#pragma unroll
                for (int mf = 0; mf < 4; mf++) {
                    int mg = wm * 8 + mf * 2 + mh;
                    uint32_t off = (uint32_t)(t * 256 + ((mg >> 3) & 1) * 128 +
                                              (((mg & 7) ^ (t & 7)) << 4));
                    ldm4t(ahf[mf], ba + off);
                }
#pragma unroll
                for (int mf = 0; mf < 4; mf++) {
                    int mg = wm * 8 + mf * 2 + mh;
                    uint32_t off = (uint32_t)(t * 256 + ((mg >> 3) & 1) * 128 +
                                              (((mg & 7) ^ (t & 7)) << 4));
                    ldm4t(alf[mf], ba + 8192 + off);
                }
            }
            // ---- B fragments ----
            if (TB == 0) {
                int brow = wn * 64 + (lane & 7) + (lane >> 4) * 8;
                int bch = kh2 * 2 + ((lane >> 3) & 1);
#pragma unroll
                for (int bi = 0; bi < 4; bi++) {
                    int row = brow + bi * 16;
                    ldm4(bhf[bi], bb + row * 128 + ((bch ^ (row & 7)) << 4));
                }
#pragma unroll
                for (int bi = 0; bi < 4; bi++) {
                    int row = brow + bi * 16;
                    ldm4(blf[bi], bb + row * 128 + (((bch + 4) ^ (row & 7)) << 4));
                }
            } else {
                int t = kh2 * 16 + ((lane >> 3) & 1) * 8 + (lane & 7);
                int nh = (lane >> 4) & 1;
#pragma unroll
                for (int bi = 0; bi < 4; bi++) {
                    int ng = wn * 8 + bi * 2 + nh;
                    uint32_t off = (uint32_t)(t * 256 + ((ng >> 3) & 1) * 128 +
                                              (((ng & 7) ^ (t & 7)) << 4));
                    ldm4t(bhf[bi], bb + off);
                }
#pragma unroll
                for (int bi = 0; bi < 4; bi++) {
                    int ng = wn * 8 + bi * 2 + nh;
                    uint32_t off = (uint32_t)(t * 256 + ((ng >> 3) & 1) * 128 +
                                              (((ng & 7) ^ (t & 7)) << 4));
                    ldm4t(blf[bi], bb + 8192 + off);
                }
            }
            // ---- 96 MMAs, term-major; per-acc order hh, hl, lh ----
#pragma unroll
            for (int mf = 0; mf < 4; mf++)
#pragma unroll
                for (int nf = 0; nf < 8; nf++)
                    mma16816(acc[mf][nf], ahf[mf], bhf[nf >> 1][2 * (nf & 1)], bhf[nf >> 1][2 * (nf & 1) + 1]);
#pragma unroll
            for (int mf = 0; mf < 4; mf++)
#pragma unroll
                for (int nf = 0; nf < 8; nf++)
                    mma16816(acc[mf][nf], ahf[mf], blf[nf >> 1][2 * (nf & 1)], blf[nf >> 1][2 * (nf & 1) + 1]);
#pragma unroll
            for (int mf = 0; mf < 4; mf++)
#pragma unroll
                for (int nf = 0; nf < 8; nf++)
                    mma16816(acc[mf][nf], alf[mf], bhf[nf >> 1][2 * (nf & 1)], bhf[nf >> 1][2 * (nf & 1) + 1]);
        }
    };

    const int nch = K >> 5;
    if (!first) __syncthreads();
    load(0, 0); CP_COMMIT();
    if (nch > 1) { load(1, 1); CP_COMMIT(); }
    for (int c = 0; c < nch; c++) {
        if (c + 1 < nch) cp_wait<1>(); else cp_wait<0>();
        __syncthreads();
        if (c + 2 < nch) { load(c + 2, (c + 2) % 3); CP_COMMIT(); }
        if (act) compute(c % 3);
    }
}

// gemm_core: K1 may be 0 at runtime. skip_wid: warp id whose LDSM+MMA are
// skipped (-1 = none); its acc stays 0 (valid only when its whole warp tile
// is masked in the epilogue).
template <int MODE, int TA1, int TB1, int TA2, int TB2>
__device__ __forceinline__ void gemm_core(
    const bf* __restrict__ A1h, const bf* __restrict__ A1l, long sA1, int lda1,
    const bf* __restrict__ B1h, const bf* __restrict__ B1l, long sB1, int ldb1, int K1,
    const bf* __restrict__ A2h, const bf* __restrict__ A2l, long sA2, int lda2,
    const bf* __restrict__ B2h, const bf* __restrict__ B2l, long sB2, int ldb2, int K2,
    void* __restrict__ Chv, void* __restrict__ Clv, long sC, int ldc,
    uint32_t sm, int bm, int bn, long z, int skip_wid = -1)
{
    const int tid = threadIdx.x, lane = tid & 31, wid = tid >> 5;
    const int wm = wid & 1, wn = (wid >> 1) & 1;
    const bool act = (wid != skip_wid);

    float acc[4][8][4];
#pragma unroll
    for (int i = 0; i < 4; i++)
#pragma unroll
        for (int j = 0; j < 8; j++)
#pragma unroll
            for (int q = 0; q < 4; q++) acc[i][j][q] = 0.0f;

    if (K1 > 0) {
        long ao = z * sA1 + (TA1 == 0 ? (long)bm * lda1 : (long)bm);
        long bo = z * sB1 + (TB1 == 0 ? (long)bn * ldb1 : (long)bn);
        run_k<TA1, TB1>(acc, sm, A1h + ao, A1l + ao, lda1,
                        B1h + bo, B1l + bo, ldb1, K1, true, tid, lane, wm, wn, act);
    }
    if (K2 > 0) {
        long ao = z * sA2 + (TA2 == 0 ? (long)bm * lda2 : (long)bm);
        long bo = z * sB2 + (TB2 == 0 ? (long)bn * ldb2 : (long)bn);
        run_k<TA2, TB2>(acc, sm, A2h + ao, A2l + ao, lda2,
                        B2h + bo, B2l + bo, ldb2, K2, (K1 <= 0), tid, lane, wm, wn, act);
    }

    // epilogue
    const long rbase = z * sC;
#pragma unroll
    for (int mf = 0; mf < 4; mf++) {
#pragma unroll
        for (int nf = 0; nf < 8; nf++) {
            float* d = acc[mf][nf];
            int r = bm + wm * 64 + mf * 16 + (lane >> 2);
            int c = bn + wn * 64 + nf * 8 + (lane & 3) * 2;
            long i0 = rbase + (long)r * ldc + c;
            long i1 = i0 + 8L * ldc;
            if (MODE == 0) {
                float* C = (float*)Chv;
                *(float2*)(C + i0) = make_float2(d[0], d[1]);
                *(float2*)(C + i1) = make_float2(d[2], d[3]);
            } else {
                float v0 = d[0], v1 = d[1], v2 = d[2], v3 = d[3];
                if (MODE == 2) {
                    if (c     > r)     v0 = 0.0f;
                    if (c + 1 > r)     v1 = 0.0f;
                    if (c     > r + 8) v2 = 0.0f;
                    if (c + 1 > r + 8) v3 = 0.0f;
                }
                uint32_t hi0, lo0, hi1, lo1;
                split2(v0, v1, hi0, lo0);
                split2(v2, v3, hi1, lo1);
                bf* Ch = (bf*)Chv; bf* Cl = (bf*)Clv;
                *(uint32_t*)(Ch + i0) = hi0;
                *(uint32_t*)(Cl + i0) = lo0;
                *(uint32_t*)(Ch + i1) = hi1;
                *(uint32_t*)(Cl + i1) = lo1;
            }
        }
    }
}

template <int MODE, int TA1, int TB1, int TA2, int TB2>
__global__ __launch_bounds__(NTHR, 2)
void gemm2(const bf* __restrict__ A1h, const bf* __restrict__ A1l, long sA1, int lda1,
           const bf* __restrict__ B1h, const bf* __restrict__ B1l, long sB1, int ldb1, int K1,
           const bf* __restrict__ A2h, const bf* __restrict__ A2l, long sA2, int lda2,
           const bf* __restrict__ B2h, const bf* __restrict__ B2l, long sB2, int ldb2, int K2,
           void* __restrict__ Chv, void* __restrict__ Clv, long sC, int ldc)
{
    extern __shared__ __align__(128) char dsm[];
    gemm_core<MODE, TA1, TB1, TA2, TB2>(
        A1h, A1l, sA1, lda1, B1h, B1l, sB1, ldb1, K1,
        A2h, A2l, sA2, lda2, B2h, B2l, sB2, ldb2, K2,
        Chv, Clv, sC, ldc,
        smem_u32(dsm), blockIdx.y * 128, blockIdx.x * 128, blockIdx.z);
}

// ---------------------------------------------------------------------------
// fused kernel, heavy-first ordering:
//   ids 0..191    : scores lower-tri tiles (K=512, heaviest) — diag tiles skip
//                   the fully-masked warp (wm=0, wn=1 -> wid 2)
//   ids 192..1215 : state GEMM CTAs (K=256)
// ---------------------------------------------------------------------------
__global__ __launch_bounds__(NTHR, 2)
void state_scores(const bf* __restrict__ qkvh, const bf* __restrict__ qkvl,
                  float* __restrict__ st,
                  bf* __restrict__ sch, bf* __restrict__ scl)
{
    extern __shared__ __align__(128) char dsm[];
    const int id = blockIdx.x;
    if (id < 3 * NCHUNKS) {
        // scores lower-tri tiles: tile 0=(0,0), 1=(1,0), 2=(1,1)
        const long z = id / 3;
        const int tile = id - (int)z * 3;
        const int bm = (tile == 0) ? 0 : 128;
        const int bn = (tile == 2) ? 128 : 0;
        const int skip = (bm == bn) ? 2 : -1;   // diag: warp tile rows<cols fully masked
        gemm_core<2, 0, 0, 0, 0>(
            qkvh, qkvl, CHQ, 3 * DIMD,
            qkvh + DIMD, qkvl + DIMD, CHQ, 3 * DIMD, DIMD,
            nullptr, nullptr, 0, 0, nullptr, nullptr, 0, 0, 0,
            sch, scl, SSQ, CCHUNK,
            smem_u32(dsm), bm, bn, z, skip);
    } else {
        // state: S_c[dv][dk] = sum_t V[t][dv] K[t][dk]
        const int t = id - 3 * NCHUNKS;
        const int x = t & 3, y = (t >> 2) & 3;
        const long z = t >> 4;
        gemm_core<0, 1, 1, 0, 0>(
            qkvh + 2 * DIMD, qkvl + 2 * DIMD, CHQ, 3 * DIMD,
            qkvh + DIMD,     qkvl + DIMD,     CHQ, 3 * DIMD, CCHUNK,
            nullptr, nullptr, 0, 0, nullptr, nullptr, 0, 0, 0,
            st, nullptr, STQ, DIMD,
            smem_u32(dsm), y * 128, x * 128, z);
    }
}

// ---------------------------------------------------------------------------
// Y kernel (1D grid, heavy-first): ids 0..255 = bm=128 tiles (full K2),
// ids 256..511 = bm=0 tiles (K2=128). K1=0 for z%16==0 (P_0 = 0).
// ---------------------------------------------------------------------------
__global__ __launch_bounds__(NTHR, 2)
void y_kern(const bf* __restrict__ qkvh, const bf* __restrict__ qkvl,
            const bf* __restrict__ ph, const bf* __restrict__ pl,
            const bf* __restrict__ sch, const bf* __restrict__ scl,
            bf* __restrict__ yh, bf* __restrict__ yl)
{
    extern __shared__ __align__(128) char dsm[];
    const int id = blockIdx.x;
    const int heavy = (id < 256);
    const int t = heavy ? id : id - 256;
    const long z = t >> 2;
    const int bn = (t & 3) * 128;
    const int bm = heavy ? 128 : 0;
    const int K1 = ((z % CHUNKS_PER_BATCH) == 0) ? 0 : DIMD;
    const int K2 = heavy ? CCHUNK : 128;
    gemm_core<1, 0, 0, 0, 1>(
        qkvh, qkvl, CHQ, 3 * DIMD, ph, pl, STQ, DIMD, K1,
        sch, scl, SSQ, CCHUNK,
        qkvh + 2 * DIMD, qkvl + 2 * DIMD, CHQ, 3 * DIMD, K2,
        yh, yl, CHY, DIMD,
        smem_u32(dsm), bm, bn, z);
}

// ---------------------------------------------------------------------------
// fused prep: weight transpose+split (ids 0..1023) + x pack (ids 1024..5119)
// ---------------------------------------------------------------------------
__global__ __launch_bounds__(256)
void prep(const float4* __restrict__ x4, bf* __restrict__ xh, bf* __restrict__ xl, int n4,
          const float* __restrict__ w0, const float* __restrict__ w1,
          const float* __restrict__ w2, const float* __restrict__ w3,
          bf* __restrict__ th, bf* __restrict__ tl)
{
    const int id = blockIdx.x;
    if (id < 1024) {
        const float* Ws[4] = {w0, w1, w2, w3};
        const int wx = id & 15, wy = (id >> 4) & 15, wz = id >> 8;
        const float* W = Ws[wz];
        __shared__ float s[32][33];
        int n0 = wx * 32, k0 = wy * 32;
        int tx = threadIdx.x & 31, ty = threadIdx.x >> 5;
#pragma unroll
        for (int i = 0; i < 4; i++)
            s[ty + 8 * i][tx] = W[(long)(k0 + ty + 8 * i) * DIMD + n0 + tx];
        __syncthreads();
#pragma unroll
        for (int i = 0; i < 4; i++) {
            float v = s[tx][ty + 8 * i];
            uint16_t h, l;
            split1(v, h, l);
            size_t o = (size_t)wz * DIMD * DIMD + (size_t)(n0 + ty + 8 * i) * DIMD + k0 + tx;
            ((uint16_t*)th)[o] = h;
            ((uint16_t*)tl)[o] = l;
        }
    } else {
        const int idp = id - 1024;
        for (int i = idp * 256 + threadIdx.x; i < n4; i += 4096 * 256) {
            float4 f = x4[i];
            uint32_t h0, l0, h1, l1;
            split2(f.x, f.y, h0, l0);
            split2(f.z, f.w, h1, l1);
            *(uint2*)(xh + (size_t)i * 4) = make_uint2(h0, h1);
            *(uint2*)(xl + (size_t)i * 4) = make_uint2(l0, l1);
        }
    }
}

__global__ __launch_bounds__(256)
void prefix_split(const float* __restrict__ st, bf* __restrict__ ph, bf* __restrict__ pl)
{
    const int e = blockIdx.x * 256 + threadIdx.x;
    const int b = blockIdx.y;
    float run = 0.0f;
    for (int c = 0; c < CHUNKS_PER_BATCH; c++) {
        size_t idx = ((size_t)(b * CHUNKS_PER_BATCH + c)) * ((size_t)DIMD * DIMD) + e;
        uint16_t h, l;
        split1(run, h, l);
        ((uint16_t*)ph)[idx] = h;
        ((uint16_t*)pl)[idx] = l;
        run += st[idx];
    }
}

// ---------------------------------------------------------------------------
// launcher
// ---------------------------------------------------------------------------
extern "C" void kernel_launch(void* const* d_in, const int* in_sizes, int n_in,
                              void* d_out, int out_size)
{
    int xi = 0;
    for (int i = 0; i < n_in; i++)
        if (in_sizes[i] == (int)(ROWS_TOTAL * DIMD)) { xi = i; break; }
    const float* W[4]; int wi = 0;
    for (int i = 0; i < n_in && wi < 4; i++) { if (i == xi) continue; W[wi++] = (const float*)d_in[i]; }
    const float* x = (const float*)d_in[xi];

    bf *xh, *xl, *qkvh, *qkvl, *yh, *yl, *wth, *wtl, *ph, *pl, *sch, *scl;
    float *st;
    cudaGetSymbolAddress((void**)&xh, g_xh);     cudaGetSymbolAddress((void**)&xl, g_xl);
    cudaGetSymbolAddress((void**)&qkvh, g_qkvh); cudaGetSymbolAddress((void**)&qkvl, g_qkvl);
    cudaGetSymbolAddress((void**)&yh, g_yh);     cudaGetSymbolAddress((void**)&yl, g_yl);
    cudaGetSymbolAddress((void**)&wth, g_wth);   cudaGetSymbolAddress((void**)&wtl, g_wtl);
    cudaGetSymbolAddress((void**)&ph, g_ph);     cudaGetSymbolAddress((void**)&pl, g_pl);
    cudaGetSymbolAddress((void**)&sch, g_sch);   cudaGetSymbolAddress((void**)&scl, g_scl);
    cudaGetSymbolAddress((void**)&st, g_st);

    cudaFuncSetAttribute(gemm2<1,0,0,0,0>, cudaFuncAttributeMaxDynamicSharedMemorySize, GSMEM);
    cudaFuncSetAttribute(gemm2<0,0,0,0,0>, cudaFuncAttributeMaxDynamicSharedMemorySize, GSMEM);
    cudaFuncSetAttribute(state_scores, cudaFuncAttributeMaxDynamicSharedMemorySize, GSMEM);
    cudaFuncSetAttribute(y_kern, cudaFuncAttributeMaxDynamicSharedMemorySize, GSMEM);

    // prep: pack x + transpose/split weights (one launch)
    prep<<<5120, 256>>>((const float4*)x, xh, xl, (int)(NE / 4),
                        W[0], W[1], W[2], W[3], wth, wtl);

    // fused q|k|v projection: [16384,1536] = x @ [Wq|Wk|Wv]
    gemm2<1,0,0,0,0><<<dim3(12, 128, 1), NTHR, GSMEM>>>(
        xh, xl, 0, DIMD, wth, wtl, 0, DIMD, DIMD,
        nullptr, nullptr, 0, 0, nullptr, nullptr, 0, 0, 0,
        qkvh, qkvl, 0, 3 * DIMD);

    // fused: scores (heavy, first) + state GEMM (one launch, 1216 CTAs)
    state_scores<<<3 * NCHUNKS + 1024, NTHR, GSMEM>>>(qkvh, qkvl, st, sch, scl);

    // exclusive prefix over chunks -> P planes
    prefix_split<<<dim3((unsigned)(STQ / 256), 4), 256>>>(st, ph, pl);

    // Y_c = Q_c @ P_c^T + scores_c @ V_c  (heavy-first 1D grid, zero skips)
    y_kern<<<512, NTHR, GSMEM>>>(qkvh, qkvl, ph, pl, sch, scl, yh, yl);

    // out = Y @ Wo (f32)
    gemm2<0,0,0,0,0><<<dim3(4, 128, 1), NTHR, GSMEM>>>(
        yh, yl, 0, DIMD, wth + 3 * STQ, wtl + 3 * STQ, 0, DIMD, DIMD,
        nullptr, nullptr, 0, 0, nullptr, nullptr, 0, 0, 0,
        d_out, nullptr, 0, DIMD);
}